// round 4
// baseline (speedup 1.0000x reference)
#include <cuda_runtime.h>
#include <cuda_bf16.h>
#include <cstdint>

#define SDIM 256
#define EDIM 32
#define VDIM 64
#define NMOL 64
#define NAF  16
#define NBT  5
#define MAXN 2048

// ---------------- device scratch (no allocs allowed) ----------------
__device__ float g_sh[MAXN * SDIM];        // s_h = silu(s@Ws+bs)
__device__ float g_T [MAXN * SDIM];        // T = s_h @ W0'
__device__ float g_raw[MAXN * 3];
__device__ float g_cp[MAXN * 3];
__device__ float g_sums[NMOL * 3];
__device__ float g_cnt[NMOL];
__device__ int   g_map[MAXN * MAXN];       // last-writer edge index per (j,i)
__device__ float g_wbw0[EDIM * SDIM];      // Wb @ W0' (tf32-rounded)
__device__ float g_cvec[SDIM];             // bb @ W0' + b0

__device__ __forceinline__ float silu_f(float x) {
    return __fdividef(x, 1.0f + __expf(-x));
}
__device__ __forceinline__ float tf32_round(float x) {
    unsigned u;
    asm("cvt.rna.tf32.f32 %0, %1;" : "=r"(u) : "f"(x));
    return __uint_as_float(u);
}

// ---------------- init: map=-1, sums/cnt=0 ----------------
__global__ void init_kernel(int N) {
    int idx = blockIdx.x * blockDim.x + threadIdx.x;
    int total = N * N;
    for (int i = idx; i < total; i += gridDim.x * blockDim.x) g_map[i] = -1;
    if (idx < NMOL * 3) g_sums[idx] = 0.0f;
    if (idx < NMOL)     g_cnt[idx]  = 0.0f;
}

// ---------------- 256x256 row GEMM over device-global scratch ----------------
// MODE 0: g_sh = silu(X_ext @ W + bias) ; MODE 1: g_T = g_sh @ W
template<int MODE>
__global__ __launch_bounds__(256) void rowgemm_kernel(
    const float* __restrict__ X_ext, const float* __restrict__ W,
    const float* __restrict__ bias, int N)
{
    const float* X = (MODE == 0) ? X_ext : (const float*)g_sh;
    float*       out = (MODE == 0) ? g_sh : g_T;

    __shared__ float sX[16 * 256];
    __shared__ float sW[32 * 256];
    int tid = threadIdx.x, lane = tid & 31, wp = tid >> 5;
    int row0 = blockIdx.x * 16;

    for (int idx = tid; idx < 16 * 256; idx += 256) {
        int g = row0 * 256 + idx;
        sX[idx] = (g < N * 256) ? X[g] : 0.0f;
    }

    float acc[8][2];
#pragma unroll
    for (int u = 0; u < 8; u++) {
        float b = (MODE == 0) ? bias[lane + 32 * u] : 0.0f;
        acc[u][0] = b; acc[u][1] = b;
    }

    for (int kc = 0; kc < 8; kc++) {
        __syncthreads();
        for (int idx = tid; idx < 8192; idx += 256)
            sW[idx] = W[kc * 32 * 256 + idx];
        __syncthreads();
#pragma unroll
        for (int kk = 0; kk < 32; kk++) {
            float w[8];
#pragma unroll
            for (int u = 0; u < 8; u++) w[u] = sW[kk * 256 + lane + 32 * u];
            float x0 = sX[(wp * 2 + 0) * 256 + kc * 32 + kk];
            float x1 = sX[(wp * 2 + 1) * 256 + kc * 32 + kk];
#pragma unroll
            for (int u = 0; u < 8; u++) {
                acc[u][0] += w[u] * x0;
                acc[u][1] += w[u] * x1;
            }
        }
    }
#pragma unroll
    for (int v = 0; v < 2; v++) {
        int r = row0 + wp * 2 + v;
        if (r < N) {
#pragma unroll
            for (int u = 0; u < 8; u++) {
                float y = acc[u][v];
                out[r * 256 + lane + 32 * u] = (MODE == 0) ? silu_f(y) : y;
            }
        }
    }
}

// ---------------- WbW0 = tf32(Wb @ W0') ; cvec = bb@W0'+b0 ----------------
__global__ void foldw_kernel(const float* __restrict__ Wb, const float* __restrict__ W0,
                             const float* __restrict__ bb, const float* __restrict__ b0)
{
    int c = threadIdx.x;
    int r = blockIdx.x;
    const float* xrow = (r < EDIM) ? (Wb + r * SDIM) : bb;
    float acc = (r < EDIM) ? 0.0f : b0[c];
#pragma unroll 16
    for (int m = 0; m < SDIM; m++)
        acc += xrow[m] * W0[m * SDIM + c];
    if (r < EDIM) g_wbw0[r * SDIM + c] = tf32_round(acc);
    else          g_cvec[c] = acc;
}

// ---------------- atoms_pred = s_h @ Wa + ba (one warp per node) ----------------
__global__ void atoms_kernel(const float* __restrict__ Wa, const float* __restrict__ ba,
                             float* __restrict__ out_atoms, int N)
{
    int wg = (blockIdx.x * blockDim.x + threadIdx.x) >> 5;
    int lane = threadIdx.x & 31;
    if (wg >= N) return;
    const float* row = g_sh + (size_t)wg * 256;
    float acc[NAF];
#pragma unroll
    for (int a = 0; a < NAF; a++) acc[a] = 0.0f;
#pragma unroll
    for (int m = 0; m < 8; m++) {
        int c = lane + 32 * m;
        float x = row[c];
#pragma unroll
        for (int a = 0; a < NAF; a++) acc[a] += x * Wa[c * NAF + a];
    }
#pragma unroll
    for (int a = 0; a < NAF; a++) {
#pragma unroll
        for (int off = 16; off; off >>= 1)
            acc[a] += __shfl_xor_sync(0xffffffffu, acc[a], off);
    }
#pragma unroll
    for (int a = 0; a < NAF; a++)
        if (lane == a) out_atoms[(size_t)wg * NAF + a] = acc[a] + ba[a];
}

// ---------------- coords / per-mol sums ----------------
__global__ void coords_kernel(const float* __restrict__ v, const float* __restrict__ p,
                              const float* __restrict__ Wc, const int* __restrict__ batch, int N)
{
    int n = (blockIdx.x * blockDim.x + threadIdx.x) >> 5;
    int lane = threadIdx.x & 31;
    if (n >= N) return;
    const float* vb = v + (size_t)n * 3 * VDIM;
    float w0 = Wc[lane], w1 = Wc[32 + lane];
    float a0 = vb[lane] * w0 + vb[32 + lane] * w1;
    float a1 = vb[64 + lane] * w0 + vb[96 + lane] * w1;
    float a2 = vb[128 + lane] * w0 + vb[160 + lane] * w1;
#pragma unroll
    for (int off = 16; off; off >>= 1) {
        a0 += __shfl_xor_sync(0xffffffffu, a0, off);
        a1 += __shfl_xor_sync(0xffffffffu, a1, off);
        a2 += __shfl_xor_sync(0xffffffffu, a2, off);
    }
    if (lane == 0) {
        int b = batch[n];
        float r0 = p[n * 3 + 0] + a0;
        float r1 = p[n * 3 + 1] + a1;
        float r2 = p[n * 3 + 2] + a2;
        g_raw[n * 3 + 0] = r0; g_raw[n * 3 + 1] = r1; g_raw[n * 3 + 2] = r2;
        atomicAdd(&g_sums[b * 3 + 0], r0);
        atomicAdd(&g_sums[b * 3 + 1], r1);
        atomicAdd(&g_sums[b * 3 + 2], r2);
        atomicAdd(&g_cnt[b], 1.0f);
    }
}

__global__ void finalize_coords_kernel(const int* __restrict__ batch,
                                       float* __restrict__ out_coords, int N)
{
    int idx = blockIdx.x * blockDim.x + threadIdx.x;
    if (idx >= N * 3) return;
    int n = idx / 3, d = idx % 3;
    int b = batch[n];
    float m = g_sums[b * 3 + d] / fmaxf(g_cnt[b], 1.0f);
    float cp = g_raw[idx] - m;
    g_cp[idx] = cp;
    out_coords[idx] = cp;
}

// ---------------- last-writer scatter ----------------
__global__ void scatter_kernel(const int* __restrict__ eidx, int N, int E)
{
    int k = blockIdx.x * blockDim.x + threadIdx.x;
    if (k >= E) return;
    int j = eidx[k];
    int i = eidx[E + k];
    atomicMax(&g_map[j * N + i], k);
}

// ---------------- fused edge network, tf32 tensor-core GEMM ----------------
// Y[64,256] = Gsym[64,32] @ WbW0[32,256]; y += T[i]+T[j]+cvec+d*w0d; z=silu(y);
// bonds = z@W1 + b1. 64 edges/block, 8 warps: warp = (edge-group g16 = wp>>1) x (col half h = wp&1).
#define SW_PITCH 264
#define SG_PITCH 72
#define EDGE_SMEM_FLOATS (32*SW_PITCH + 32*SG_PITCH + 5*256 + 256 + 256 + 2*64*5 + 64 + 32)
#define EDGE_SMEM_BYTES  (EDGE_SMEM_FLOATS * 4)

__device__ __forceinline__ void mma_tf32(float& c0, float& c1, float& c2, float& c3,
                                         unsigned a0, unsigned a1, unsigned a2, unsigned a3,
                                         unsigned b0, unsigned b1) {
    asm volatile(
        "mma.sync.aligned.m16n8k8.row.col.f32.tf32.tf32.f32 "
        "{%0,%1,%2,%3}, {%4,%5,%6,%7}, {%8,%9}, {%0,%1,%2,%3};\n"
        : "+f"(c0), "+f"(c1), "+f"(c2), "+f"(c3)
        : "r"(a0), "r"(a1), "r"(a2), "r"(a3), "r"(b0), "r"(b1));
}

__device__ __forceinline__ void ffma2(unsigned long long& acc,
                                      unsigned long long a, unsigned long long b) {
    asm("fma.rn.f32x2 %0, %1, %2, %0;" : "+l"(acc) : "l"(a), "l"(b));
}
__device__ __forceinline__ float2 unpack2(unsigned long long x) {
    float2 r;
    asm("mov.b64 {%0, %1}, %2;" : "=f"(r.x), "=f"(r.y) : "l"(x));
    return r;
}
__device__ __forceinline__ unsigned long long pack2(float x, float y) {
    unsigned long long r;
    asm("mov.b64 %0, {%1, %2};" : "=l"(r) : "r"(__float_as_uint(x)), "r"(__float_as_uint(y)));
    return r;
}

__global__ __launch_bounds__(256, 2) void edge_kernel(
    const float* __restrict__ e, const int* __restrict__ eidx,
    const float* __restrict__ W0, const float* __restrict__ W1,
    const float* __restrict__ b1,
    float* __restrict__ out_bonds, int N, int E)
{
    extern __shared__ float sm[];
    float* sW   = sm;                     // [32][264] WbW0 (tf32 bits)
    float* sgT  = sW  + 32 * SW_PITCH;    // [32][72]  Gsym^T (tf32 bits), k-major
    float* sW1T = sgT + 32 * SG_PITCH;    // [5][256]
    float* scv  = sW1T + 5 * 256;         // [256]
    float* sw0  = scv + 256;              // [256]  W0 row 256 (d weights)
    float* sPB  = sw0 + 256;              // [2][64][5] partial bonds
    float* sd   = sPB + 2 * 64 * 5;       // [64]
    int*   sI   = (int*)(sd + 64);        // reuse tail: [64]... (within 32 pad + overlay below)
    // k1/k2 temporaries overlay sPB (sPB only written after post-fill sync)
    int*   sK1  = (int*)sPB;
    int*   sK2  = sK1 + 64;
    int*   sJ2  = sK2 + 64;               // j index (overlay, but needed later!) -- see below

    // NOTE: sI must persist through epilogue; place it in dedicated space:
    // we reserved 64 floats at sd+64? No — use separate statics below.
    __shared__ int sIi[64];
    __shared__ int sJj[64];

    int tid = threadIdx.x, lane = tid & 31, wp = tid >> 5;
    int e0 = blockIdx.x * 64;

    // ---- stage weights ----
    for (int idx = tid; idx < EDIM * SDIM; idx += 256) {
        int q = idx >> 8, c = idx & 255;
        sW[q * SW_PITCH + c] = g_wbw0[idx];
    }
    for (int idx = tid; idx < 5 * 256; idx += 256) {
        int b = idx >> 8, c = idx & 255;
        sW1T[idx] = W1[c * NBT + b];
    }
    if (tid < 256) { scv[tid] = g_cvec[tid]; sw0[tid] = W0[256 * 256 + tid]; }

    // ---- per-edge meta ----
    if (tid < 64) {
        int eg = e0 + tid;
        int i = 0, j = 0, k1 = -1, k2 = -1;
        float dval = 0.0f;
        if (eg < E) {
            j = eidx[eg];
            i = eidx[E + eg];
            k1 = g_map[j * N + i];
            k2 = g_map[i * N + j];
            float dx = g_cp[i * 3 + 0] - g_cp[j * 3 + 0];
            float dy = g_cp[i * 3 + 1] - g_cp[j * 3 + 1];
            float dz = g_cp[i * 3 + 2] - g_cp[j * 3 + 2];
            dval = dx * dx + dy * dy + dz * dz;
        }
        sIi[tid] = i; sJj[tid] = j; sK1[tid] = k1; sK2[tid] = k2; sd[tid] = dval;
    }
    __syncthreads();

    // ---- symmetrized e rows -> sgT[k][m] (tf32-rounded) ----
    for (int idx = tid; idx < 64 * 32; idx += 256) {
        int el = idx >> 5, q = idx & 31;
        int k1 = sK1[el], k2 = sK2[el];
        float g1 = (k1 >= 0) ? e[(size_t)k1 * EDIM + q] : 0.0f;
        float g2 = (k2 >= 0) ? e[(size_t)k2 * EDIM + q] : 0.0f;
        sgT[q * SG_PITCH + el] = tf32_round(0.5f * (g1 + g2));
    }
    __syncthreads();

    // ---- tensor-core GEMM: per warp 16 edges x 128 cols ----
    int h = wp & 1, g16 = wp >> 1;
    int m0 = g16 * 16;
    int gid = lane >> 2, tig = lane & 3;

    unsigned afr[4][4];
#pragma unroll
    for (int kk = 0; kk < 4; kk++) {
        int kr = kk * 8 + tig;
        afr[kk][0] = __float_as_uint(sgT[kr * SG_PITCH + m0 + gid]);
        afr[kk][1] = __float_as_uint(sgT[kr * SG_PITCH + m0 + gid + 8]);
        afr[kk][2] = __float_as_uint(sgT[(kr + 4) * SG_PITCH + m0 + gid]);
        afr[kk][3] = __float_as_uint(sgT[(kr + 4) * SG_PITCH + m0 + gid + 8]);
    }

    float acc[16][4];
#pragma unroll
    for (int nt = 0; nt < 16; nt++) {
        float c0 = 0.0f, c1 = 0.0f, c2 = 0.0f, c3 = 0.0f;
        int nb = h * 128 + nt * 8 + gid;
#pragma unroll
        for (int kk = 0; kk < 4; kk++) {
            int kr = kk * 8 + tig;
            unsigned b0 = __float_as_uint(sW[kr * SW_PITCH + nb]);
            unsigned b1 = __float_as_uint(sW[(kr + 4) * SW_PITCH + nb]);
            mma_tf32(c0, c1, c2, c3,
                     afr[kk][0], afr[kk][1], afr[kk][2], afr[kk][3], b0, b1);
        }
        acc[nt][0] = c0; acc[nt][1] = c1; acc[nt][2] = c2; acc[nt][3] = c3;
    }

    // ---- epilogue: rows r0 = m0+gid (acc[.][0,1]) and r1 = r0+8 (acc[.][2,3]) ----
#pragma unroll
    for (int half = 0; half < 2; half++) {
        int r = m0 + gid + half * 8;
        int i = sIi[r], jn = sJj[r];
        float dv = sd[r];
        const float* Ti = g_T + (size_t)i * 256;
        const float* Tj = g_T + (size_t)jn * 256;

        unsigned long long pbp[NBT];
#pragma unroll
        for (int b = 0; b < NBT; b++) pbp[b] = 0ull;

#pragma unroll
        for (int nt = 0; nt < 16; nt++) {
            int col0 = h * 128 + nt * 8 + 2 * tig;
            float2 ti = *(const float2*)&Ti[col0];
            float2 tj = *(const float2*)&Tj[col0];
            float2 cv = *(const float2*)&scv[col0];
            float2 wd = *(const float2*)&sw0[col0];
            float y0 = acc[nt][half * 2 + 0] + cv.x + ti.x + tj.x + dv * wd.x;
            float y1 = acc[nt][half * 2 + 1] + cv.y + ti.y + tj.y + dv * wd.y;
            float z0 = silu_f(y0);
            float z1 = silu_f(y1);
            unsigned long long zp = pack2(z0, z1);
#pragma unroll
            for (int b = 0; b < NBT; b++) {
                unsigned long long w1p = *(const unsigned long long*)&sW1T[b * 256 + col0];
                ffma2(pbp[b], zp, w1p);
            }
        }
        float pb[NBT];
#pragma unroll
        for (int b = 0; b < NBT; b++) {
            float2 u = unpack2(pbp[b]);
            pb[b] = u.x + u.y;
            pb[b] += __shfl_xor_sync(0xffffffffu, pb[b], 1);
            pb[b] += __shfl_xor_sync(0xffffffffu, pb[b], 2);
        }
        if (tig == 0) {
#pragma unroll
            for (int b = 0; b < NBT; b++)
                sPB[h * 320 + r * 5 + b] = pb[b];
        }
    }
    __syncthreads();

    // ---- merge halves + bias, write ----
    for (int t = tid; t < 64 * NBT; t += 256) {
        int el = t / NBT, b = t % NBT;
        int eg = e0 + el;
        if (eg < E)
            out_bonds[(size_t)eg * NBT + b] = sPB[t] + sPB[320 + t] + b1[b];
    }
}

// ---------------- launch ----------------
extern "C" void kernel_launch(void* const* d_in, const int* in_sizes, int n_in,
                              void* d_out, int out_size)
{
    const float* s     = (const float*)d_in[0];
    const float* v     = (const float*)d_in[1];
    const float* p     = (const float*)d_in[2];
    const float* e     = (const float*)d_in[3];
    const int*   batch = (const int*)d_in[4];
    const int*   eidx  = (const int*)d_in[5];
    const float* Ws = (const float*)d_in[6];
    const float* bs = (const float*)d_in[7];
    const float* Wc = (const float*)d_in[8];
    const float* Wa = (const float*)d_in[9];
    const float* ba = (const float*)d_in[10];
    const float* Wb = (const float*)d_in[11];
    const float* bb = (const float*)d_in[12];
    const float* W0 = (const float*)d_in[13];
    const float* b0 = (const float*)d_in[14];
    const float* W1 = (const float*)d_in[15];
    const float* b1 = (const float*)d_in[16];

    int N = in_sizes[0] / SDIM;
    int E = in_sizes[5] / 2;

    float* out        = (float*)d_out;
    float* out_coords = out;
    float* out_atoms  = out + (size_t)N * 3;
    float* out_bonds  = out_atoms + (size_t)N * NAF;

    cudaFuncSetAttribute(edge_kernel, cudaFuncAttributeMaxDynamicSharedMemorySize,
                         EDGE_SMEM_BYTES);

    int init_blocks = (N * N + 1023) / 1024;
    init_kernel<<<init_blocks, 1024>>>(N);

    rowgemm_kernel<0><<<(N + 15) / 16, 256>>>(s, Ws, bs, N);
    rowgemm_kernel<1><<<(N + 15) / 16, 256>>>(nullptr, W0, nullptr, N);

    foldw_kernel<<<EDIM + 1, 256>>>(Wb, W0, bb, b0);

    atoms_kernel<<<(N * 32 + 255) / 256, 256>>>(Wa, ba, out_atoms, N);

    coords_kernel<<<(N * 32 + 255) / 256, 256>>>(v, p, Wc, batch, N);

    finalize_coords_kernel<<<(N * 3 + 255) / 256, 256>>>(batch, out_coords, N);

    scatter_kernel<<<(E + 255) / 256, 256>>>(eidx, N, E);

    edge_kernel<<<(E + 63) / 64, 256, EDGE_SMEM_BYTES>>>(
        e, eidx, W0, W1, b1, out_bonds, N, E);
}

// round 5
// speedup vs baseline: 1.0182x; 1.0182x over previous
#include <cuda_runtime.h>
#include <cuda_bf16.h>
#include <cstdint>

#define SDIM 256
#define EDIM 32
#define VDIM 64
#define NMOL 64
#define NAF  16
#define NBT  5
#define MAXN 2048

// ---------------- device scratch ----------------
__device__ float g_sh[MAXN * SDIM];
__device__ float g_T [MAXN * SDIM];
__device__ float g_raw[MAXN * 3];
__device__ float g_cp[MAXN * 3];
__device__ float g_sums[NMOL * 3];
__device__ float g_cnt[NMOL];
__device__ int   g_map[MAXN * MAXN];
__device__ float g_wbw0[EDIM * SDIM];      // tf32-rounded Wb@W0'
__device__ float g_cvec[SDIM];             // bb@W0' + b0

__device__ __forceinline__ float silu_f(float x) {
    return __fdividef(x, 1.0f + __expf(-x));
}
__device__ __forceinline__ float tf32_round(float x) {
    unsigned u;
    asm("cvt.rna.tf32.f32 %0, %1;" : "=r"(u) : "f"(x));
    return __uint_as_float(u);
}

// ---------------- init ----------------
__global__ void init_kernel(int N) {
    int idx = blockIdx.x * blockDim.x + threadIdx.x;
    int total = N * N;
    for (int i = idx; i < total; i += gridDim.x * blockDim.x) g_map[i] = -1;
    if (idx < NMOL * 3) g_sums[idx] = 0.0f;
    if (idx < NMOL)     g_cnt[idx]  = 0.0f;
}

// ---------------- fused node kernel: s_h, T, atoms ----------------
// GEMM1: s_h = silu(s@Ws+bs) -> g_sh + smem ; GEMM2: T = s_h@W0 -> g_T ;
// atoms = s_h@Wa + ba.  16 rows/block.
__global__ __launch_bounds__(256) void node_kernel(
    const float* __restrict__ s, const float* __restrict__ Ws,
    const float* __restrict__ bs, const float* __restrict__ W0,
    const float* __restrict__ Wa, const float* __restrict__ ba,
    float* __restrict__ out_atoms, int N)
{
    __shared__ float sX[16 * 256];
    __shared__ float sW[32 * 256];
    int tid = threadIdx.x, lane = tid & 31, wp = tid >> 5;
    int row0 = blockIdx.x * 16;

    for (int idx = tid; idx < 16 * 256; idx += 256) {
        int g = row0 * 256 + idx;
        sX[idx] = (g < N * 256) ? s[g] : 0.0f;
    }

    // ---- GEMM1: silu(s@Ws+bs) ----
    float acc[8][2];
#pragma unroll
    for (int u = 0; u < 8; u++) {
        float b = bs[lane + 32 * u];
        acc[u][0] = b; acc[u][1] = b;
    }
    for (int kc = 0; kc < 8; kc++) {
        __syncthreads();
        for (int idx = tid; idx < 8192; idx += 256)
            sW[idx] = Ws[kc * 32 * 256 + idx];
        __syncthreads();
#pragma unroll
        for (int kk = 0; kk < 32; kk++) {
            float w[8];
#pragma unroll
            for (int u = 0; u < 8; u++) w[u] = sW[kk * 256 + lane + 32 * u];
            float x0 = sX[(wp * 2 + 0) * 256 + kc * 32 + kk];
            float x1 = sX[(wp * 2 + 1) * 256 + kc * 32 + kk];
#pragma unroll
            for (int u = 0; u < 8; u++) {
                acc[u][0] += w[u] * x0;
                acc[u][1] += w[u] * x1;
            }
        }
    }
    __syncthreads();   // everyone done reading sX(s)
#pragma unroll
    for (int v = 0; v < 2; v++) {
        int r = row0 + wp * 2 + v;
#pragma unroll
        for (int u = 0; u < 8; u++) {
            float z = silu_f(acc[u][v]);
            sX[(wp * 2 + v) * 256 + lane + 32 * u] = z;
            if (r < N) g_sh[r * 256 + lane + 32 * u] = z;
        }
    }

    // ---- GEMM2: T = s_h @ W0 ----
#pragma unroll
    for (int u = 0; u < 8; u++) { acc[u][0] = 0.0f; acc[u][1] = 0.0f; }
    for (int kc = 0; kc < 8; kc++) {
        __syncthreads();
        for (int idx = tid; idx < 8192; idx += 256)
            sW[idx] = W0[kc * 32 * 256 + idx];
        __syncthreads();
#pragma unroll
        for (int kk = 0; kk < 32; kk++) {
            float w[8];
#pragma unroll
            for (int u = 0; u < 8; u++) w[u] = sW[kk * 256 + lane + 32 * u];
            float x0 = sX[(wp * 2 + 0) * 256 + kc * 32 + kk];
            float x1 = sX[(wp * 2 + 1) * 256 + kc * 32 + kk];
#pragma unroll
            for (int u = 0; u < 8; u++) {
                acc[u][0] += w[u] * x0;
                acc[u][1] += w[u] * x1;
            }
        }
    }
#pragma unroll
    for (int v = 0; v < 2; v++) {
        int r = row0 + wp * 2 + v;
        if (r < N) {
#pragma unroll
            for (int u = 0; u < 8; u++)
                g_T[r * 256 + lane + 32 * u] = acc[u][v];
        }
    }

    // ---- atoms: s_h @ Wa + ba (s_h is in sX) ----
    __syncthreads();
    for (int idx = tid; idx < SDIM * NAF; idx += 256) sW[idx] = Wa[idx];
    __syncthreads();
#pragma unroll
    for (int v = 0; v < 2; v++) {
        int rl = wp * 2 + v;
        int r = row0 + rl;
        float a[NAF];
#pragma unroll
        for (int q = 0; q < NAF; q++) a[q] = 0.0f;
#pragma unroll
        for (int m = 0; m < 8; m++) {
            int c = lane + 32 * m;
            float x = sX[rl * 256 + c];
#pragma unroll
            for (int q = 0; q < NAF; q++) a[q] += x * sW[c * NAF + q];
        }
#pragma unroll
        for (int q = 0; q < NAF; q++) {
#pragma unroll
            for (int off = 16; off; off >>= 1)
                a[q] += __shfl_xor_sync(0xffffffffu, a[q], off);
        }
        if (r < N && lane < NAF)
            out_atoms[(size_t)r * NAF + lane] = a[lane] + ba[lane];
    }
}

// ---------------- foldw: 8 accumulators to force MLP ----------------
__global__ void foldw_kernel(const float* __restrict__ Wb, const float* __restrict__ W0,
                             const float* __restrict__ bb, const float* __restrict__ b0)
{
    int c = threadIdx.x;
    int r = blockIdx.x;
    const float* xrow = (r < EDIM) ? (Wb + r * SDIM) : bb;
    float a0 = 0, a1 = 0, a2 = 0, a3 = 0, a4 = 0, a5 = 0, a6 = 0, a7 = 0;
    for (int m = 0; m < SDIM; m += 8) {
        float x0 = xrow[m+0], x1 = xrow[m+1], x2 = xrow[m+2], x3 = xrow[m+3];
        float x4 = xrow[m+4], x5 = xrow[m+5], x6 = xrow[m+6], x7 = xrow[m+7];
        float w0 = W0[(m+0)*SDIM+c], w1 = W0[(m+1)*SDIM+c];
        float w2 = W0[(m+2)*SDIM+c], w3 = W0[(m+3)*SDIM+c];
        float w4 = W0[(m+4)*SDIM+c], w5 = W0[(m+5)*SDIM+c];
        float w6 = W0[(m+6)*SDIM+c], w7 = W0[(m+7)*SDIM+c];
        a0 += x0*w0; a1 += x1*w1; a2 += x2*w2; a3 += x3*w3;
        a4 += x4*w4; a5 += x5*w5; a6 += x6*w6; a7 += x7*w7;
    }
    float acc = ((a0+a1)+(a2+a3)) + ((a4+a5)+(a6+a7));
    if (r < EDIM) g_wbw0[r * SDIM + c] = tf32_round(acc);
    else          g_cvec[c] = acc + b0[c];
}

// ---------------- coords / per-mol sums ----------------
__global__ void coords_kernel(const float* __restrict__ v, const float* __restrict__ p,
                              const float* __restrict__ Wc, const int* __restrict__ batch, int N)
{
    int n = (blockIdx.x * blockDim.x + threadIdx.x) >> 5;
    int lane = threadIdx.x & 31;
    if (n >= N) return;
    const float* vb = v + (size_t)n * 3 * VDIM;
    float w0 = Wc[lane], w1 = Wc[32 + lane];
    float a0 = vb[lane] * w0 + vb[32 + lane] * w1;
    float a1 = vb[64 + lane] * w0 + vb[96 + lane] * w1;
    float a2 = vb[128 + lane] * w0 + vb[160 + lane] * w1;
#pragma unroll
    for (int off = 16; off; off >>= 1) {
        a0 += __shfl_xor_sync(0xffffffffu, a0, off);
        a1 += __shfl_xor_sync(0xffffffffu, a1, off);
        a2 += __shfl_xor_sync(0xffffffffu, a2, off);
    }
    if (lane == 0) {
        int b = batch[n];
        float r0 = p[n * 3 + 0] + a0;
        float r1 = p[n * 3 + 1] + a1;
        float r2 = p[n * 3 + 2] + a2;
        g_raw[n * 3 + 0] = r0; g_raw[n * 3 + 1] = r1; g_raw[n * 3 + 2] = r2;
        atomicAdd(&g_sums[b * 3 + 0], r0);
        atomicAdd(&g_sums[b * 3 + 1], r1);
        atomicAdd(&g_sums[b * 3 + 2], r2);
        atomicAdd(&g_cnt[b], 1.0f);
    }
}

__global__ void finalize_coords_kernel(const int* __restrict__ batch,
                                       float* __restrict__ out_coords, int N)
{
    int idx = blockIdx.x * blockDim.x + threadIdx.x;
    if (idx >= N * 3) return;
    int n = idx / 3, d = idx % 3;
    int b = batch[n];
    float m = g_sums[b * 3 + d] / fmaxf(g_cnt[b], 1.0f);
    float cp = g_raw[idx] - m;
    g_cp[idx] = cp;
    out_coords[idx] = cp;
}

// ---------------- last-writer scatter ----------------
__global__ void scatter_kernel(const int* __restrict__ eidx, int N, int E)
{
    int k = blockIdx.x * blockDim.x + threadIdx.x;
    if (k >= E) return;
    int j = eidx[k];
    int i = eidx[E + k];
    atomicMax(&g_map[j * N + i], k);
}

// ---------------- fused edge network, tf32 MMA, streaming epilogue ----------------
#define SW_PITCH 264
#define SG_PITCH 72
#define EDGE_SMEM_FLOATS (32*SW_PITCH + 32*SG_PITCH + 5*256 + 256 + 256 + 2*64*5)
#define EDGE_SMEM_BYTES  (EDGE_SMEM_FLOATS * 4)

__device__ __forceinline__ void mma_tf32(float& c0, float& c1, float& c2, float& c3,
                                         unsigned a0, unsigned a1, unsigned a2, unsigned a3,
                                         unsigned b0, unsigned b1) {
    asm volatile(
        "mma.sync.aligned.m16n8k8.row.col.f32.tf32.tf32.f32 "
        "{%0,%1,%2,%3}, {%4,%5,%6,%7}, {%8,%9}, {%0,%1,%2,%3};\n"
        : "+f"(c0), "+f"(c1), "+f"(c2), "+f"(c3)
        : "r"(a0), "r"(a1), "r"(a2), "r"(a3), "r"(b0), "r"(b1));
}
__device__ __forceinline__ void ffma2(unsigned long long& acc,
                                      unsigned long long a, unsigned long long b) {
    asm("fma.rn.f32x2 %0, %1, %2, %0;" : "+l"(acc) : "l"(a), "l"(b));
}
__device__ __forceinline__ float2 unpack2(unsigned long long x) {
    float2 r;
    asm("mov.b64 {%0, %1}, %2;" : "=f"(r.x), "=f"(r.y) : "l"(x));
    return r;
}
__device__ __forceinline__ unsigned long long pack2(float x, float y) {
    unsigned long long r;
    asm("mov.b64 %0, {%1, %2};" : "=l"(r) : "r"(__float_as_uint(x)), "r"(__float_as_uint(y)));
    return r;
}

__global__ __launch_bounds__(256, 2) void edge_kernel(
    const float* __restrict__ e, const int* __restrict__ eidx,
    const float* __restrict__ W0, const float* __restrict__ W1,
    const float* __restrict__ b1,
    float* __restrict__ out_bonds, int N, int E)
{
    extern __shared__ float sm[];
    float* sW   = sm;                     // [32][264] WbW0
    float* sgT  = sW  + 32 * SW_PITCH;    // [32][72]  Gsym^T, k-major
    float* sW1T = sgT + 32 * SG_PITCH;    // [5][256]
    float* scv  = sW1T + 5 * 256;         // [256]
    float* sw0  = scv + 256;              // [256]
    float* sPB  = sw0 + 256;              // [2][64][5]

    __shared__ int   sIi[64], sJj[64], sK1[64], sK2[64];
    __shared__ float sd[64];

    int tid = threadIdx.x, lane = tid & 31, wp = tid >> 5;
    int e0 = blockIdx.x * 64;

    // ---- stage weights ----
    for (int idx = tid; idx < EDIM * SDIM; idx += 256) {
        int q = idx >> 8, c = idx & 255;
        sW[q * SW_PITCH + c] = g_wbw0[idx];
    }
    for (int idx = tid; idx < 5 * 256; idx += 256) {
        int b = idx >> 8, c = idx & 255;
        sW1T[idx] = W1[c * NBT + b];
    }
    if (tid < 256) { scv[tid] = g_cvec[tid]; sw0[tid] = W0[256 * 256 + tid]; }

    // ---- per-edge meta ----
    if (tid < 64) {
        int eg = e0 + tid;
        int i = 0, j = 0, k1 = -1, k2 = -1;
        float dval = 0.0f;
        if (eg < E) {
            j = eidx[eg];
            i = eidx[E + eg];
            k1 = g_map[j * N + i];
            k2 = g_map[i * N + j];
            float dx = g_cp[i * 3 + 0] - g_cp[j * 3 + 0];
            float dy = g_cp[i * 3 + 1] - g_cp[j * 3 + 1];
            float dz = g_cp[i * 3 + 2] - g_cp[j * 3 + 2];
            dval = dx * dx + dy * dy + dz * dz;
        }
        sIi[tid] = i; sJj[tid] = j; sK1[tid] = k1; sK2[tid] = k2; sd[tid] = dval;
    }
    __syncthreads();

    // ---- symmetrized e -> sgT (tf32) ----
    for (int idx = tid; idx < 64 * 32; idx += 256) {
        int el = idx >> 5, q = idx & 31;
        int k1 = sK1[el], k2 = sK2[el];
        float g1 = (k1 >= 0) ? e[(size_t)k1 * EDIM + q] : 0.0f;
        float g2 = (k2 >= 0) ? e[(size_t)k2 * EDIM + q] : 0.0f;
        sgT[q * SG_PITCH + el] = tf32_round(0.5f * (g1 + g2));
    }
    __syncthreads();

    // ---- warp layout: h = col half, g16 = 16-edge group ----
    int h = wp & 1, g16 = wp >> 1;
    int m0 = g16 * 16;
    int gid = lane >> 2, tig = lane & 3;

    unsigned afr[4][4];
#pragma unroll
    for (int kk = 0; kk < 4; kk++) {
        int kr = kk * 8 + tig;
        afr[kk][0] = __float_as_uint(sgT[kr * SG_PITCH + m0 + gid]);
        afr[kk][1] = __float_as_uint(sgT[kr * SG_PITCH + m0 + gid + 8]);
        afr[kk][2] = __float_as_uint(sgT[(kr + 4) * SG_PITCH + m0 + gid]);
        afr[kk][3] = __float_as_uint(sgT[(kr + 4) * SG_PITCH + m0 + gid + 8]);
    }

    int r0 = m0 + gid, r1 = r0 + 8;
    const float* Ti0 = g_T + (size_t)sIi[r0] * 256;
    const float* Tj0 = g_T + (size_t)sJj[r0] * 256;
    const float* Ti1 = g_T + (size_t)sIi[r1] * 256;
    const float* Tj1 = g_T + (size_t)sJj[r1] * 256;
    float dv0 = sd[r0], dv1 = sd[r1];

    unsigned long long pbp0[NBT], pbp1[NBT];
#pragma unroll
    for (int b = 0; b < NBT; b++) { pbp0[b] = 0ull; pbp1[b] = 0ull; }

#pragma unroll 4
    for (int nt = 0; nt < 16; nt++) {
        int nb = h * 128 + nt * 8 + gid;
        float c0 = 0.0f, c1 = 0.0f, c2 = 0.0f, c3 = 0.0f;
#pragma unroll
        for (int kk = 0; kk < 4; kk++) {
            int kr = kk * 8 + tig;
            unsigned b0 = __float_as_uint(sW[kr * SW_PITCH + nb]);
            unsigned b1 = __float_as_uint(sW[(kr + 4) * SW_PITCH + nb]);
            mma_tf32(c0, c1, c2, c3,
                     afr[kk][0], afr[kk][1], afr[kk][2], afr[kk][3], b0, b1);
        }

        int col0 = h * 128 + nt * 8 + 2 * tig;
        float2 cv = *(const float2*)&scv[col0];
        float2 wd = *(const float2*)&sw0[col0];
        float2 ti0 = *(const float2*)&Ti0[col0];
        float2 tj0 = *(const float2*)&Tj0[col0];
        float2 ti1 = *(const float2*)&Ti1[col0];
        float2 tj1 = *(const float2*)&Tj1[col0];

        float base0 = cv.x, base1 = cv.y;
        float z00 = silu_f(c0 + base0 + ti0.x + tj0.x + dv0 * wd.x);
        float z01 = silu_f(c1 + base1 + ti0.y + tj0.y + dv0 * wd.y);
        float z10 = silu_f(c2 + base0 + ti1.x + tj1.x + dv1 * wd.x);
        float z11 = silu_f(c3 + base1 + ti1.y + tj1.y + dv1 * wd.y);
        unsigned long long zp0 = pack2(z00, z01);
        unsigned long long zp1 = pack2(z10, z11);
#pragma unroll
        for (int b = 0; b < NBT; b++) {
            unsigned long long w1p = *(const unsigned long long*)&sW1T[b * 256 + col0];
            ffma2(pbp0[b], zp0, w1p);
            ffma2(pbp1[b], zp1, w1p);
        }
    }

    // ---- reduce within quad (4 lanes), stage partials ----
#pragma unroll
    for (int b = 0; b < NBT; b++) {
        float2 u0 = unpack2(pbp0[b]);
        float2 u1 = unpack2(pbp1[b]);
        float p0 = u0.x + u0.y;
        float p1 = u1.x + u1.y;
        p0 += __shfl_xor_sync(0xffffffffu, p0, 1);
        p0 += __shfl_xor_sync(0xffffffffu, p0, 2);
        p1 += __shfl_xor_sync(0xffffffffu, p1, 1);
        p1 += __shfl_xor_sync(0xffffffffu, p1, 2);
        if (tig == 0) {
            sPB[h * 320 + r0 * 5 + b] = p0;
            sPB[h * 320 + r1 * 5 + b] = p1;
        }
    }
    __syncthreads();

    // ---- merge halves + bias, write ----
    for (int t = tid; t < 64 * NBT; t += 256) {
        int el = t / NBT, b = t % NBT;
        int eg = e0 + el;
        if (eg < E)
            out_bonds[(size_t)eg * NBT + b] = sPB[t] + sPB[320 + t] + b1[b];
    }
}

// ---------------- launch ----------------
extern "C" void kernel_launch(void* const* d_in, const int* in_sizes, int n_in,
                              void* d_out, int out_size)
{
    const float* s     = (const float*)d_in[0];
    const float* v     = (const float*)d_in[1];
    const float* p     = (const float*)d_in[2];
    const float* e     = (const float*)d_in[3];
    const int*   batch = (const int*)d_in[4];
    const int*   eidx  = (const int*)d_in[5];
    const float* Ws = (const float*)d_in[6];
    const float* bs = (const float*)d_in[7];
    const float* Wc = (const float*)d_in[8];
    const float* Wa = (const float*)d_in[9];
    const float* ba = (const float*)d_in[10];
    const float* Wb = (const float*)d_in[11];
    const float* bb = (const float*)d_in[12];
    const float* W0 = (const float*)d_in[13];
    const float* b0 = (const float*)d_in[14];
    const float* W1 = (const float*)d_in[15];
    const float* b1 = (const float*)d_in[16];

    int N = in_sizes[0] / SDIM;
    int E = in_sizes[5] / 2;

    float* out        = (float*)d_out;
    float* out_coords = out;
    float* out_atoms  = out + (size_t)N * 3;
    float* out_bonds  = out_atoms + (size_t)N * NAF;

    cudaFuncSetAttribute(edge_kernel, cudaFuncAttributeMaxDynamicSharedMemorySize,
                         EDGE_SMEM_BYTES);

    int init_blocks = (N * N + 1023) / 1024;
    init_kernel<<<init_blocks, 1024>>>(N);

    node_kernel<<<(N + 15) / 16, 256>>>(s, Ws, bs, W0, Wa, ba, out_atoms, N);

    foldw_kernel<<<EDIM + 1, 256>>>(Wb, W0, bb, b0);

    coords_kernel<<<(N * 32 + 255) / 256, 256>>>(v, p, Wc, batch, N);

    finalize_coords_kernel<<<(N * 3 + 255) / 256, 256>>>(batch, out_coords, N);

    scatter_kernel<<<(E + 255) / 256, 256>>>(eidx, N, E);

    edge_kernel<<<(E + 63) / 64, 256, EDGE_SMEM_BYTES>>>(
        e, eidx, W0, W1, b1, out_bonds, N, E);
}

// round 6
// speedup vs baseline: 1.2370x; 1.2148x over previous
#include <cuda_runtime.h>
#include <cuda_bf16.h>
#include <cstdint>

#define SDIM 256
#define EDIM 32
#define VDIM 64
#define NMOL 64
#define NAF  16
#define NBT  5
#define MAXN 2048
#define ETILE 128

// ---------------- device scratch ----------------
__device__ float g_sh[MAXN * SDIM];
__device__ float g_T [MAXN * SDIM];
__device__ float g_raw[MAXN * 3];
__device__ float g_sums[NMOL * 3];
__device__ float g_cnt[NMOL];
__device__ int   g_map[MAXN * MAXN];
__device__ float g_wbw0[EDIM * SDIM];      // Wb @ W0'
__device__ float g_cvec[SDIM];             // bb @ W0' + b0

__device__ __forceinline__ float silu_f(float x) {
    return __fdividef(x, 1.0f + __expf(-x));
}

// ---------------- k0: init ----------------
__global__ void init_kernel(int N) {
    int idx = blockIdx.x * blockDim.x + threadIdx.x;
    int total = N * N;
    for (int i = idx; i < total; i += gridDim.x * blockDim.x) g_map[i] = -1;
    if (idx < NMOL * 3) g_sums[idx] = 0.0f;
    if (idx < NMOL)     g_cnt[idx]  = 0.0f;
}

// ---------------- k1: fused node work (+foldw tail blocks) ----------------
// blocks [0,nodeBlocks): s_h=silu(s@Ws+bs)->g_sh ; T=s_h@W0->g_T ; atoms head
// blocks [nodeBlocks, nodeBlocks+33): foldw rows (WbW0, cvec)
__global__ __launch_bounds__(256) void node_fold_kernel(
    const float* __restrict__ s, const float* __restrict__ Ws,
    const float* __restrict__ bs, const float* __restrict__ W0,
    const float* __restrict__ Wa, const float* __restrict__ ba,
    const float* __restrict__ Wb, const float* __restrict__ bb,
    const float* __restrict__ b0,
    float* __restrict__ out_atoms, int N, int nodeBlocks)
{
    if (blockIdx.x >= nodeBlocks) {
        // ---- foldw path ----
        int c = threadIdx.x;
        int r = blockIdx.x - nodeBlocks;
        const float* xrow = (r < EDIM) ? (Wb + r * SDIM) : bb;
        float a0 = 0, a1 = 0, a2 = 0, a3 = 0, a4 = 0, a5 = 0, a6 = 0, a7 = 0;
        for (int m = 0; m < SDIM; m += 8) {
            float x0 = xrow[m+0], x1 = xrow[m+1], x2 = xrow[m+2], x3 = xrow[m+3];
            float x4 = xrow[m+4], x5 = xrow[m+5], x6 = xrow[m+6], x7 = xrow[m+7];
            a0 += x0 * W0[(m+0)*SDIM+c]; a1 += x1 * W0[(m+1)*SDIM+c];
            a2 += x2 * W0[(m+2)*SDIM+c]; a3 += x3 * W0[(m+3)*SDIM+c];
            a4 += x4 * W0[(m+4)*SDIM+c]; a5 += x5 * W0[(m+5)*SDIM+c];
            a6 += x6 * W0[(m+6)*SDIM+c]; a7 += x7 * W0[(m+7)*SDIM+c];
        }
        float acc = ((a0+a1)+(a2+a3)) + ((a4+a5)+(a6+a7));
        if (r < EDIM) g_wbw0[r * SDIM + c] = acc;
        else          g_cvec[c] = acc + b0[c];
        return;
    }

    __shared__ float sX[16 * 256];
    __shared__ float sW[32 * 256];
    int tid = threadIdx.x, lane = tid & 31, wp = tid >> 5;
    int row0 = blockIdx.x * 16;

    for (int idx = tid; idx < 16 * 256; idx += 256) {
        int g = row0 * 256 + idx;
        sX[idx] = (g < N * 256) ? s[g] : 0.0f;
    }

    // GEMM1: silu(s@Ws+bs)
    float acc[8][2];
#pragma unroll
    for (int u = 0; u < 8; u++) {
        float b = bs[lane + 32 * u];
        acc[u][0] = b; acc[u][1] = b;
    }
    for (int kc = 0; kc < 8; kc++) {
        __syncthreads();
        for (int idx = tid; idx < 8192; idx += 256)
            sW[idx] = Ws[kc * 32 * 256 + idx];
        __syncthreads();
#pragma unroll
        for (int kk = 0; kk < 32; kk++) {
            float w[8];
#pragma unroll
            for (int u = 0; u < 8; u++) w[u] = sW[kk * 256 + lane + 32 * u];
            float x0 = sX[(wp * 2 + 0) * 256 + kc * 32 + kk];
            float x1 = sX[(wp * 2 + 1) * 256 + kc * 32 + kk];
#pragma unroll
            for (int u = 0; u < 8; u++) {
                acc[u][0] += w[u] * x0;
                acc[u][1] += w[u] * x1;
            }
        }
    }
    __syncthreads();
#pragma unroll
    for (int v = 0; v < 2; v++) {
        int r = row0 + wp * 2 + v;
#pragma unroll
        for (int u = 0; u < 8; u++) {
            float z = silu_f(acc[u][v]);
            sX[(wp * 2 + v) * 256 + lane + 32 * u] = z;
            if (r < N) g_sh[r * 256 + lane + 32 * u] = z;
        }
    }

    // GEMM2: T = s_h @ W0
#pragma unroll
    for (int u = 0; u < 8; u++) { acc[u][0] = 0.0f; acc[u][1] = 0.0f; }
    for (int kc = 0; kc < 8; kc++) {
        __syncthreads();
        for (int idx = tid; idx < 8192; idx += 256)
            sW[idx] = W0[kc * 32 * 256 + idx];
        __syncthreads();
#pragma unroll
        for (int kk = 0; kk < 32; kk++) {
            float w[8];
#pragma unroll
            for (int u = 0; u < 8; u++) w[u] = sW[kk * 256 + lane + 32 * u];
            float x0 = sX[(wp * 2 + 0) * 256 + kc * 32 + kk];
            float x1 = sX[(wp * 2 + 1) * 256 + kc * 32 + kk];
#pragma unroll
            for (int u = 0; u < 8; u++) {
                acc[u][0] += w[u] * x0;
                acc[u][1] += w[u] * x1;
            }
        }
    }
#pragma unroll
    for (int v = 0; v < 2; v++) {
        int r = row0 + wp * 2 + v;
        if (r < N) {
#pragma unroll
            for (int u = 0; u < 8; u++)
                g_T[r * 256 + lane + 32 * u] = acc[u][v];
        }
    }

    // atoms head (s_h in sX)
    __syncthreads();
    for (int idx = tid; idx < SDIM * NAF; idx += 256) sW[idx] = Wa[idx];
    __syncthreads();
#pragma unroll
    for (int v = 0; v < 2; v++) {
        int rl = wp * 2 + v;
        int r = row0 + rl;
        float a[NAF];
#pragma unroll
        for (int q = 0; q < NAF; q++) a[q] = 0.0f;
#pragma unroll
        for (int m = 0; m < 8; m++) {
            int c = lane + 32 * m;
            float x = sX[rl * 256 + c];
#pragma unroll
            for (int q = 0; q < NAF; q++) a[q] += x * sW[c * NAF + q];
        }
#pragma unroll
        for (int q = 0; q < NAF; q++) {
#pragma unroll
            for (int off = 16; off; off >>= 1)
                a[q] += __shfl_xor_sync(0xffffffffu, a[q], off);
        }
        if (r < N && lane < NAF)
            out_atoms[(size_t)r * NAF + lane] = a[lane] + ba[lane];
    }
}

// ---------------- k2: scatter (blocks < scatBlocks) + coords sums ----------------
__global__ void prep_kernel(const int* __restrict__ eidx,
                            const float* __restrict__ v, const float* __restrict__ p,
                            const float* __restrict__ Wc, const int* __restrict__ batch,
                            int N, int E, int scatBlocks)
{
    int tid = threadIdx.x;
    if ((int)blockIdx.x < scatBlocks) {
        int k = blockIdx.x * 256 + tid;
        if (k < E) {
            int j = eidx[k];
            int i = eidx[E + k];
            atomicMax(&g_map[j * N + i], k);
        }
        return;
    }
    // coords: 8 warps/block, 1 node per warp
    int n = (blockIdx.x - scatBlocks) * 8 + (tid >> 5);
    int lane = tid & 31;
    if (n >= N) return;
    const float* vb = v + (size_t)n * 3 * VDIM;
    float w0 = Wc[lane], w1 = Wc[32 + lane];
    float a0 = vb[lane] * w0 + vb[32 + lane] * w1;
    float a1 = vb[64 + lane] * w0 + vb[96 + lane] * w1;
    float a2 = vb[128 + lane] * w0 + vb[160 + lane] * w1;
#pragma unroll
    for (int off = 16; off; off >>= 1) {
        a0 += __shfl_xor_sync(0xffffffffu, a0, off);
        a1 += __shfl_xor_sync(0xffffffffu, a1, off);
        a2 += __shfl_xor_sync(0xffffffffu, a2, off);
    }
    if (lane == 0) {
        int b = batch[n];
        float r0 = p[n * 3 + 0] + a0;
        float r1 = p[n * 3 + 1] + a1;
        float r2 = p[n * 3 + 2] + a2;
        g_raw[n * 3 + 0] = r0; g_raw[n * 3 + 1] = r1; g_raw[n * 3 + 2] = r2;
        atomicAdd(&g_sums[b * 3 + 0], r0);
        atomicAdd(&g_sums[b * 3 + 1], r1);
        atomicAdd(&g_sums[b * 3 + 2], r2);
        atomicAdd(&g_cnt[b], 1.0f);
    }
}

// ---------------- k3 (PROFILED SLOT): fused edge network ----------------
// y = T[i]+T[j]+e_sym@WbW0+cvec+d*w0d ; z=silu(y) ; bonds = z@W1+b1
// Centering computed inline from g_raw/g_sums/g_cnt.
#define EDGE_SMEM_BYTES ((8192 + 1280 + 256 + 256 + 4096 + 128) * 4 + 4 * 128 * 4)

__device__ __forceinline__ unsigned long long dup_f32x2(float x) {
    unsigned long long r;
    asm("mov.b64 %0, {%1, %1};" : "=l"(r) : "r"(__float_as_uint(x)));
    return r;
}
__device__ __forceinline__ void ffma2(unsigned long long& acc,
                                      unsigned long long a, unsigned long long b) {
    asm("fma.rn.f32x2 %0, %1, %2, %0;" : "+l"(acc) : "l"(a), "l"(b));
}
__device__ __forceinline__ float2 unpack2(unsigned long long x) {
    float2 r;
    asm("mov.b64 {%0, %1}, %2;" : "=f"(r.x), "=f"(r.y) : "l"(x));
    return r;
}

__global__ __launch_bounds__(256, 2) void edge_kernel(
    const float* __restrict__ e, const int* __restrict__ eidx,
    const int* __restrict__ batch,
    const float* __restrict__ W0, const float* __restrict__ W1,
    const float* __restrict__ b1,
    float* __restrict__ out_bonds, int N, int E)
{
    extern __shared__ float sm[];
    float* sW   = sm;                 // [32][256] WbW0
    float* sW1T = sW + 8192;          // [5][256]
    float* scv  = sW1T + 1280;        // [256]
    float* sw0  = scv + 256;          // [256]
    float* sg   = sw0 + 256;          // [128][32]
    float* sd   = sg + 4096;          // [128]
    int*   sI   = (int*)(sd + 128);
    int*   sJ   = sI + 128;
    int*   sK1  = sJ + 128;
    int*   sK2  = sK1 + 128;

    int tid = threadIdx.x, lane = tid & 31, wp = tid >> 5;
    int e0 = blockIdx.x * ETILE;

    for (int idx = tid; idx < 8192; idx += 256) sW[idx] = g_wbw0[idx];
    for (int idx = tid; idx < 1280; idx += 256) {
        int b = idx >> 8, c = idx & 255;
        sW1T[idx] = W1[c * NBT + b];
    }
    if (tid < 256) { scv[tid] = g_cvec[tid]; sw0[tid] = W0[256 * 256 + tid]; }

    // ---- per-edge meta (incl. inline centering) ----
    if (tid < ETILE) {
        int eg = e0 + tid;
        int i = 0, j = 0, k1 = -1, k2 = -1;
        float dval = 0.0f;
        if (eg < E) {
            j = eidx[eg];
            i = eidx[E + eg];
            k1 = g_map[j * N + i];
            k2 = g_map[i * N + j];
            int bi = batch[i], bj = batch[j];
            float inv_i = 1.0f / fmaxf(g_cnt[bi], 1.0f);
            float inv_j = 1.0f / fmaxf(g_cnt[bj], 1.0f);
            float dx = (g_raw[i*3+0] - g_sums[bi*3+0]*inv_i)
                     - (g_raw[j*3+0] - g_sums[bj*3+0]*inv_j);
            float dy = (g_raw[i*3+1] - g_sums[bi*3+1]*inv_i)
                     - (g_raw[j*3+1] - g_sums[bj*3+1]*inv_j);
            float dz = (g_raw[i*3+2] - g_sums[bi*3+2]*inv_i)
                     - (g_raw[j*3+2] - g_sums[bj*3+2]*inv_j);
            dval = dx * dx + dy * dy + dz * dz;
        }
        sI[tid] = i; sJ[tid] = j; sK1[tid] = k1; sK2[tid] = k2; sd[tid] = dval;
    }
    __syncthreads();

    // ---- symmetrized e rows ----
    for (int idx = tid; idx < ETILE * 32; idx += 256) {
        int el = idx >> 5, q = idx & 31;
        int k1 = sK1[el], k2 = sK2[el];
        float g1 = (k1 >= 0) ? e[(size_t)k1 * EDIM + q] : 0.0f;
        float g2 = (k2 >= 0) ? e[(size_t)k2 * EDIM + q] : 0.0f;
        sg[idx] = 0.5f * (g1 + g2);
    }
    __syncthreads();

    // ---- each warp: 16 edges in 2 subpasses of 8 ----
    for (int sub = 0; sub < 2; sub++) {
        int base = wp * 16 + sub * 8;

        float gv[8];
#pragma unroll
        for (int v = 0; v < 8; v++) gv[v] = sg[(base + v) * 32 + lane];

        unsigned long long acc[4][8];
#pragma unroll
        for (int t = 0; t < 4; t++)
#pragma unroll
            for (int v = 0; v < 8; v++) acc[t][v] = 0ull;

#pragma unroll 8
        for (int q = 0; q < 32; q++) {
            unsigned long long wq[4];
#pragma unroll
            for (int t = 0; t < 4; t++)
                wq[t] = *(const unsigned long long*)&sW[q * 256 + 2 * lane + 64 * t];
#pragma unroll
            for (int v = 0; v < 8; v++) {
                float gq = __shfl_sync(0xffffffffu, gv[v], q);
                unsigned long long g2 = dup_f32x2(gq);
#pragma unroll
                for (int t = 0; t < 4; t++) ffma2(acc[t][v], wq[t], g2);
            }
        }

        // ---- epilogue per edge ----
#pragma unroll 2
        for (int v = 0; v < 8; v++) {
            int el = base + v;
            int eg = e0 + el;
            int i = sI[el], jn = sJ[el];
            float dval = sd[el];
            const float* Ti = g_T + (size_t)i * 256;
            const float* Tj = g_T + (size_t)jn * 256;

            unsigned long long zp[4];
#pragma unroll
            for (int t = 0; t < 4; t++) {
                int c0 = 2 * lane + 64 * t;
                float2 a  = unpack2(acc[t][v]);
                float2 ti = *(const float2*)&Ti[c0];
                float2 tj = *(const float2*)&Tj[c0];
                float2 cv = *(const float2*)&scv[c0];
                float2 wd = *(const float2*)&sw0[c0];
                float y0 = a.x + cv.x + ti.x + tj.x + dval * wd.x;
                float y1 = a.y + cv.y + ti.y + tj.y + dval * wd.y;
                float z0 = silu_f(y0);
                float z1 = silu_f(y1);
                unsigned long long zpk;
                asm("mov.b64 %0, {%1, %2};" : "=l"(zpk)
                    : "r"(__float_as_uint(z0)), "r"(__float_as_uint(z1)));
                zp[t] = zpk;
            }

            unsigned long long pbp[NBT];
#pragma unroll
            for (int b = 0; b < NBT; b++) pbp[b] = 0ull;
#pragma unroll
            for (int t = 0; t < 4; t++) {
                int c0 = 2 * lane + 64 * t;
#pragma unroll
                for (int b = 0; b < NBT; b++) {
                    unsigned long long w1p =
                        *(const unsigned long long*)&sW1T[b * 256 + c0];
                    ffma2(pbp[b], zp[t], w1p);
                }
            }
            float pb[NBT];
#pragma unroll
            for (int b = 0; b < NBT; b++) {
                float2 u = unpack2(pbp[b]);
                pb[b] = u.x + u.y;
            }
#pragma unroll
            for (int b = 0; b < NBT; b++) {
#pragma unroll
                for (int off = 16; off; off >>= 1)
                    pb[b] += __shfl_xor_sync(0xffffffffu, pb[b], off);
            }
            if (lane == 0 && eg < E) {
#pragma unroll
                for (int b = 0; b < NBT; b++)
                    out_bonds[(size_t)eg * NBT + b] = pb[b] + b1[b];
            }
        }
    }
}

// ---------------- k4: finalize coords output ----------------
__global__ void finalize_coords_kernel(const int* __restrict__ batch,
                                       float* __restrict__ out_coords, int N)
{
    int idx = blockIdx.x * blockDim.x + threadIdx.x;
    if (idx >= N * 3) return;
    int n = idx / 3, d = idx % 3;
    int b = batch[n];
    float m = g_sums[b * 3 + d] / fmaxf(g_cnt[b], 1.0f);
    out_coords[idx] = g_raw[idx] - m;
}

// ---------------- launch ----------------
extern "C" void kernel_launch(void* const* d_in, const int* in_sizes, int n_in,
                              void* d_out, int out_size)
{
    const float* s     = (const float*)d_in[0];
    const float* v     = (const float*)d_in[1];
    const float* p     = (const float*)d_in[2];
    const float* e     = (const float*)d_in[3];
    const int*   batch = (const int*)d_in[4];
    const int*   eidx  = (const int*)d_in[5];
    const float* Ws = (const float*)d_in[6];
    const float* bs = (const float*)d_in[7];
    const float* Wc = (const float*)d_in[8];
    const float* Wa = (const float*)d_in[9];
    const float* ba = (const float*)d_in[10];
    const float* Wb = (const float*)d_in[11];
    const float* bb = (const float*)d_in[12];
    const float* W0 = (const float*)d_in[13];
    const float* b0 = (const float*)d_in[14];
    const float* W1 = (const float*)d_in[15];
    const float* b1 = (const float*)d_in[16];

    int N = in_sizes[0] / SDIM;
    int E = in_sizes[5] / 2;

    float* out        = (float*)d_out;
    float* out_coords = out;
    float* out_atoms  = out + (size_t)N * 3;
    float* out_bonds  = out_atoms + (size_t)N * NAF;

    cudaFuncSetAttribute(edge_kernel, cudaFuncAttributeMaxDynamicSharedMemorySize,
                         EDGE_SMEM_BYTES);

    // launch 0: init
    int init_blocks = (N * N + 1023) / 1024;
    init_kernel<<<init_blocks, 1024>>>(N);

    // launch 1: node GEMMs + atoms + foldw (tail blocks)
    int nodeBlocks = (N + 15) / 16;
    node_fold_kernel<<<nodeBlocks + EDIM + 1, 256>>>(
        s, Ws, bs, W0, Wa, ba, Wb, bb, b0, out_atoms, N, nodeBlocks);

    // launch 2: scatter + coords sums
    int scatBlocks = (E + 255) / 256;
    int coordBlocks = (N + 7) / 8;
    prep_kernel<<<scatBlocks + coordBlocks, 256>>>(
        eidx, v, p, Wc, batch, N, E, scatBlocks);

    // launch 3 (PROFILED): fused edge network
    edge_kernel<<<(E + ETILE - 1) / ETILE, 256, EDGE_SMEM_BYTES>>>(
        e, eidx, batch, W0, W1, b1, out_bonds, N, E);

    // launch 4: coords output
    finalize_coords_kernel<<<(N * 3 + 255) / 256, 256>>>(batch, out_coords, N);
}

// round 7
// speedup vs baseline: 1.3169x; 1.0646x over previous
#include <cuda_runtime.h>
#include <cuda_bf16.h>
#include <cstdint>

#define SDIM 256
#define EDIM 32
#define VDIM 64
#define NMOL 64
#define NAF  16
#define NBT  5
#define MAXN 2048
#define ETILE 128

// ---------------- device scratch ----------------
__device__ float g_sh[MAXN * SDIM];
__device__ float g_T [MAXN * SDIM];
__device__ float g_raw[MAXN * 3];
__device__ float g_sums[NMOL * 3];
__device__ float g_cnt[NMOL];
__device__ int   g_map[MAXN * MAXN];
__device__ float g_wbw0[EDIM * SDIM];      // Wb @ W0'
__device__ float g_cvec[SDIM];             // bb @ W0' + b0

__device__ __forceinline__ float silu_f(float x) {
    return __fdividef(x, 1.0f + __expf(-x));
}
// silu via MUFU.TANH: silu(x) = h + h*tanh(h), h = x/2
__device__ __forceinline__ float silu_t(float x) {
    float h = 0.5f * x;
    float t;
    asm("tanh.approx.f32 %0, %1;" : "=f"(t) : "f"(h));
    return fmaf(h, t, h);
}

// ---------------- k0: init ----------------
__global__ void init_kernel(int N) {
    int idx = blockIdx.x * blockDim.x + threadIdx.x;
    int total = N * N;
    for (int i = idx; i < total; i += gridDim.x * blockDim.x) g_map[i] = -1;
    if (idx < NMOL * 3) g_sums[idx] = 0.0f;
    if (idx < NMOL)     g_cnt[idx]  = 0.0f;
}

// ---------------- k1: fused node work (+foldw tail blocks) ----------------
__global__ __launch_bounds__(256) void node_fold_kernel(
    const float* __restrict__ s, const float* __restrict__ Ws,
    const float* __restrict__ bs, const float* __restrict__ W0,
    const float* __restrict__ Wa, const float* __restrict__ ba,
    const float* __restrict__ Wb, const float* __restrict__ bb,
    const float* __restrict__ b0,
    float* __restrict__ out_atoms, int N, int nodeBlocks)
{
    if (blockIdx.x >= nodeBlocks) {
        int c = threadIdx.x;
        int r = blockIdx.x - nodeBlocks;
        const float* xrow = (r < EDIM) ? (Wb + r * SDIM) : bb;
        float a0 = 0, a1 = 0, a2 = 0, a3 = 0, a4 = 0, a5 = 0, a6 = 0, a7 = 0;
        for (int m = 0; m < SDIM; m += 8) {
            float x0 = xrow[m+0], x1 = xrow[m+1], x2 = xrow[m+2], x3 = xrow[m+3];
            float x4 = xrow[m+4], x5 = xrow[m+5], x6 = xrow[m+6], x7 = xrow[m+7];
            a0 += x0 * W0[(m+0)*SDIM+c]; a1 += x1 * W0[(m+1)*SDIM+c];
            a2 += x2 * W0[(m+2)*SDIM+c]; a3 += x3 * W0[(m+3)*SDIM+c];
            a4 += x4 * W0[(m+4)*SDIM+c]; a5 += x5 * W0[(m+5)*SDIM+c];
            a6 += x6 * W0[(m+6)*SDIM+c]; a7 += x7 * W0[(m+7)*SDIM+c];
        }
        float acc = ((a0+a1)+(a2+a3)) + ((a4+a5)+(a6+a7));
        if (r < EDIM) g_wbw0[r * SDIM + c] = acc;
        else          g_cvec[c] = acc + b0[c];
        return;
    }

    __shared__ float sX[16 * 256];
    __shared__ float sW[32 * 256];
    int tid = threadIdx.x, lane = tid & 31, wp = tid >> 5;
    int row0 = blockIdx.x * 16;

    for (int idx = tid; idx < 16 * 256; idx += 256) {
        int g = row0 * 256 + idx;
        sX[idx] = (g < N * 256) ? s[g] : 0.0f;
    }

    float acc[8][2];
#pragma unroll
    for (int u = 0; u < 8; u++) {
        float b = bs[lane + 32 * u];
        acc[u][0] = b; acc[u][1] = b;
    }
    for (int kc = 0; kc < 8; kc++) {
        __syncthreads();
        for (int idx = tid; idx < 8192; idx += 256)
            sW[idx] = Ws[kc * 32 * 256 + idx];
        __syncthreads();
#pragma unroll
        for (int kk = 0; kk < 32; kk++) {
            float w[8];
#pragma unroll
            for (int u = 0; u < 8; u++) w[u] = sW[kk * 256 + lane + 32 * u];
            float x0 = sX[(wp * 2 + 0) * 256 + kc * 32 + kk];
            float x1 = sX[(wp * 2 + 1) * 256 + kc * 32 + kk];
#pragma unroll
            for (int u = 0; u < 8; u++) {
                acc[u][0] += w[u] * x0;
                acc[u][1] += w[u] * x1;
            }
        }
    }
    __syncthreads();
#pragma unroll
    for (int v = 0; v < 2; v++) {
        int r = row0 + wp * 2 + v;
#pragma unroll
        for (int u = 0; u < 8; u++) {
            float z = silu_f(acc[u][v]);
            sX[(wp * 2 + v) * 256 + lane + 32 * u] = z;
            if (r < N) g_sh[r * 256 + lane + 32 * u] = z;
        }
    }

#pragma unroll
    for (int u = 0; u < 8; u++) { acc[u][0] = 0.0f; acc[u][1] = 0.0f; }
    for (int kc = 0; kc < 8; kc++) {
        __syncthreads();
        for (int idx = tid; idx < 8192; idx += 256)
            sW[idx] = W0[kc * 32 * 256 + idx];
        __syncthreads();
#pragma unroll
        for (int kk = 0; kk < 32; kk++) {
            float w[8];
#pragma unroll
            for (int u = 0; u < 8; u++) w[u] = sW[kk * 256 + lane + 32 * u];
            float x0 = sX[(wp * 2 + 0) * 256 + kc * 32 + kk];
            float x1 = sX[(wp * 2 + 1) * 256 + kc * 32 + kk];
#pragma unroll
            for (int u = 0; u < 8; u++) {
                acc[u][0] += w[u] * x0;
                acc[u][1] += w[u] * x1;
            }
        }
    }
#pragma unroll
    for (int v = 0; v < 2; v++) {
        int r = row0 + wp * 2 + v;
        if (r < N) {
#pragma unroll
            for (int u = 0; u < 8; u++)
                g_T[r * 256 + lane + 32 * u] = acc[u][v];
        }
    }

    __syncthreads();
    for (int idx = tid; idx < SDIM * NAF; idx += 256) sW[idx] = Wa[idx];
    __syncthreads();
#pragma unroll
    for (int v = 0; v < 2; v++) {
        int rl = wp * 2 + v;
        int r = row0 + rl;
        float a[NAF];
#pragma unroll
        for (int q = 0; q < NAF; q++) a[q] = 0.0f;
#pragma unroll
        for (int m = 0; m < 8; m++) {
            int c = lane + 32 * m;
            float x = sX[rl * 256 + c];
#pragma unroll
            for (int q = 0; q < NAF; q++) a[q] += x * sW[c * NAF + q];
        }
#pragma unroll
        for (int q = 0; q < NAF; q++) {
#pragma unroll
            for (int off = 16; off; off >>= 1)
                a[q] += __shfl_xor_sync(0xffffffffu, a[q], off);
        }
        if (r < N && lane < NAF)
            out_atoms[(size_t)r * NAF + lane] = a[lane] + ba[lane];
    }
}

// ---------------- k2: scatter + coords sums ----------------
__global__ void prep_kernel(const int* __restrict__ eidx,
                            const float* __restrict__ v, const float* __restrict__ p,
                            const float* __restrict__ Wc, const int* __restrict__ batch,
                            int N, int E, int scatBlocks)
{
    int tid = threadIdx.x;
    if ((int)blockIdx.x < scatBlocks) {
        int k = blockIdx.x * 256 + tid;
        if (k < E) {
            int j = eidx[k];
            int i = eidx[E + k];
            atomicMax(&g_map[j * N + i], k);
        }
        return;
    }
    int n = (blockIdx.x - scatBlocks) * 8 + (tid >> 5);
    int lane = tid & 31;
    if (n >= N) return;
    const float* vb = v + (size_t)n * 3 * VDIM;
    float w0 = Wc[lane], w1 = Wc[32 + lane];
    float a0 = vb[lane] * w0 + vb[32 + lane] * w1;
    float a1 = vb[64 + lane] * w0 + vb[96 + lane] * w1;
    float a2 = vb[128 + lane] * w0 + vb[160 + lane] * w1;
#pragma unroll
    for (int off = 16; off; off >>= 1) {
        a0 += __shfl_xor_sync(0xffffffffu, a0, off);
        a1 += __shfl_xor_sync(0xffffffffu, a1, off);
        a2 += __shfl_xor_sync(0xffffffffu, a2, off);
    }
    if (lane == 0) {
        int b = batch[n];
        float r0 = p[n * 3 + 0] + a0;
        float r1 = p[n * 3 + 1] + a1;
        float r2 = p[n * 3 + 2] + a2;
        g_raw[n * 3 + 0] = r0; g_raw[n * 3 + 1] = r1; g_raw[n * 3 + 2] = r2;
        atomicAdd(&g_sums[b * 3 + 0], r0);
        atomicAdd(&g_sums[b * 3 + 1], r1);
        atomicAdd(&g_sums[b * 3 + 2], r2);
        atomicAdd(&g_cnt[b], 1.0f);
    }
}

// ---------------- k3 (PROFILED): fused edge network ----------------
#define EDGE_SMEM_BYTES ((8192 + 1280 + 256 + 256 + 4096 + 128) * 4 + 4 * 128 * 4)

__device__ __forceinline__ unsigned long long dup_f32x2(float x) {
    unsigned long long r;
    asm("mov.b64 %0, {%1, %1};" : "=l"(r) : "r"(__float_as_uint(x)));
    return r;
}
__device__ __forceinline__ void ffma2(unsigned long long& acc,
                                      unsigned long long a, unsigned long long b) {
    asm("fma.rn.f32x2 %0, %1, %2, %0;" : "+l"(acc) : "l"(a), "l"(b));
}
__device__ __forceinline__ float2 unpack2(unsigned long long x) {
    float2 r;
    asm("mov.b64 {%0, %1}, %2;" : "=f"(r.x), "=f"(r.y) : "l"(x));
    return r;
}

__global__ __launch_bounds__(256, 3) void edge_kernel(
    const float* __restrict__ e, const int* __restrict__ eidx,
    const int* __restrict__ batch,
    const float* __restrict__ W0, const float* __restrict__ W1,
    const float* __restrict__ b1,
    float* __restrict__ out_bonds, int N, int E)
{
    extern __shared__ float sm[];
    float* sW   = sm;                 // [32][256] WbW0
    float* sW1T = sW + 8192;          // [5][256]
    float* scv  = sW1T + 1280;        // [256]
    float* sw0  = scv + 256;          // [256]
    float* sg   = sw0 + 256;          // [128][32]
    float* sd   = sg + 4096;          // [128]
    int*   sI   = (int*)(sd + 128);
    int*   sJ   = sI + 128;
    int*   sK1  = sJ + 128;
    int*   sK2  = sK1 + 128;

    int tid = threadIdx.x, lane = tid & 31, wp = tid >> 5;
    int e0 = blockIdx.x * ETILE;

    for (int idx = tid; idx < 8192; idx += 256) sW[idx] = g_wbw0[idx];
    for (int idx = tid; idx < 1280; idx += 256) {
        int b = idx >> 8, c = idx & 255;
        sW1T[idx] = W1[c * NBT + b];
    }
    if (tid < 256) { scv[tid] = g_cvec[tid]; sw0[tid] = W0[256 * 256 + tid]; }

    // ---- per-edge meta (incl. inline centering) ----
    if (tid < ETILE) {
        int eg = e0 + tid;
        int i = 0, j = 0, k1 = -1, k2 = -1;
        float dval = 0.0f;
        if (eg < E) {
            j = eidx[eg];
            i = eidx[E + eg];
            k1 = g_map[j * N + i];
            k2 = g_map[i * N + j];
            int bi = batch[i], bj = batch[j];
            float inv_i = 1.0f / fmaxf(g_cnt[bi], 1.0f);
            float inv_j = 1.0f / fmaxf(g_cnt[bj], 1.0f);
            float dx = (g_raw[i*3+0] - g_sums[bi*3+0]*inv_i)
                     - (g_raw[j*3+0] - g_sums[bj*3+0]*inv_j);
            float dy = (g_raw[i*3+1] - g_sums[bi*3+1]*inv_i)
                     - (g_raw[j*3+1] - g_sums[bj*3+1]*inv_j);
            float dz = (g_raw[i*3+2] - g_sums[bi*3+2]*inv_i)
                     - (g_raw[j*3+2] - g_sums[bj*3+2]*inv_j);
            dval = dx * dx + dy * dy + dz * dz;
        }
        sI[tid] = i; sJ[tid] = j; sK1[tid] = k1; sK2[tid] = k2; sd[tid] = dval;
    }
    __syncthreads();

    // ---- symmetrized e rows ----
    for (int idx = tid; idx < ETILE * 32; idx += 256) {
        int el = idx >> 5, q = idx & 31;
        int k1 = sK1[el], k2 = sK2[el];
        float g1 = (k1 >= 0) ? e[(size_t)k1 * EDIM + q] : 0.0f;
        float g2 = (k2 >= 0) ? e[(size_t)k2 * EDIM + q] : 0.0f;
        sg[idx] = 0.5f * (g1 + g2);
    }
    __syncthreads();

    // ---- each warp: 16 edges, 4 subpasses of 4 (small acc tile -> 3 CTAs/SM) ----
    for (int sub = 0; sub < 4; sub++) {
        int base = wp * 16 + sub * 4;

        float gv[4];
#pragma unroll
        for (int v = 0; v < 4; v++) gv[v] = sg[(base + v) * 32 + lane];

        unsigned long long acc[4][4];
#pragma unroll
        for (int t = 0; t < 4; t++)
#pragma unroll
            for (int v = 0; v < 4; v++) acc[t][v] = 0ull;

#pragma unroll 8
        for (int q = 0; q < 32; q++) {
            unsigned long long wq[4];
#pragma unroll
            for (int t = 0; t < 4; t++)
                wq[t] = *(const unsigned long long*)&sW[q * 256 + 2 * lane + 64 * t];
#pragma unroll
            for (int v = 0; v < 4; v++) {
                float gq = __shfl_sync(0xffffffffu, gv[v], q);
                unsigned long long g2 = dup_f32x2(gq);
#pragma unroll
                for (int t = 0; t < 4; t++) ffma2(acc[t][v], wq[t], g2);
            }
        }

        // ---- epilogue per edge ----
#pragma unroll
        for (int v = 0; v < 4; v++) {
            int el = base + v;
            int eg = e0 + el;
            int i = sI[el], jn = sJ[el];
            float dval = sd[el];
            const float* Ti = g_T + (size_t)i * 256;
            const float* Tj = g_T + (size_t)jn * 256;

            unsigned long long pbp[NBT];
#pragma unroll
            for (int b = 0; b < NBT; b++) pbp[b] = 0ull;

#pragma unroll
            for (int t = 0; t < 4; t++) {
                int c0 = 2 * lane + 64 * t;
                float2 a  = unpack2(acc[t][v]);
                float2 ti = *(const float2*)&Ti[c0];
                float2 tj = *(const float2*)&Tj[c0];
                float2 cv = *(const float2*)&scv[c0];
                float2 wd = *(const float2*)&sw0[c0];
                float y0 = a.x + cv.x + ti.x + tj.x + dval * wd.x;
                float y1 = a.y + cv.y + ti.y + tj.y + dval * wd.y;
                float z0 = silu_t(y0);
                float z1 = silu_t(y1);
                unsigned long long zp;
                asm("mov.b64 %0, {%1, %2};" : "=l"(zp)
                    : "r"(__float_as_uint(z0)), "r"(__float_as_uint(z1)));
#pragma unroll
                for (int b = 0; b < NBT; b++) {
                    unsigned long long w1p =
                        *(const unsigned long long*)&sW1T[b * 256 + c0];
                    ffma2(pbp[b], zp, w1p);
                }
            }
            float pb[NBT];
#pragma unroll
            for (int b = 0; b < NBT; b++) {
                float2 u = unpack2(pbp[b]);
                pb[b] = u.x + u.y;
            }
#pragma unroll
            for (int b = 0; b < NBT; b++) {
#pragma unroll
                for (int off = 16; off; off >>= 1)
                    pb[b] += __shfl_xor_sync(0xffffffffu, pb[b], off);
            }
            if (lane == 0 && eg < E) {
#pragma unroll
                for (int b = 0; b < NBT; b++)
                    out_bonds[(size_t)eg * NBT + b] = pb[b] + b1[b];
            }
        }
    }
}

// ---------------- k4: finalize coords output ----------------
__global__ void finalize_coords_kernel(const int* __restrict__ batch,
                                       float* __restrict__ out_coords, int N)
{
    int idx = blockIdx.x * blockDim.x + threadIdx.x;
    if (idx >= N * 3) return;
    int n = idx / 3, d = idx % 3;
    int b = batch[n];
    float m = g_sums[b * 3 + d] / fmaxf(g_cnt[b], 1.0f);
    out_coords[idx] = g_raw[idx] - m;
}

// ---------------- launch ----------------
extern "C" void kernel_launch(void* const* d_in, const int* in_sizes, int n_in,
                              void* d_out, int out_size)
{
    const float* s     = (const float*)d_in[0];
    const float* v     = (const float*)d_in[1];
    const float* p     = (const float*)d_in[2];
    const float* e     = (const float*)d_in[3];
    const int*   batch = (const int*)d_in[4];
    const int*   eidx  = (const int*)d_in[5];
    const float* Ws = (const float*)d_in[6];
    const float* bs = (const float*)d_in[7];
    const float* Wc = (const float*)d_in[8];
    const float* Wa = (const float*)d_in[9];
    const float* ba = (const float*)d_in[10];
    const float* Wb = (const float*)d_in[11];
    const float* bb = (const float*)d_in[12];
    const float* W0 = (const float*)d_in[13];
    const float* b0 = (const float*)d_in[14];
    const float* W1 = (const float*)d_in[15];
    const float* b1 = (const float*)d_in[16];

    int N = in_sizes[0] / SDIM;
    int E = in_sizes[5] / 2;

    float* out        = (float*)d_out;
    float* out_coords = out;
    float* out_atoms  = out + (size_t)N * 3;
    float* out_bonds  = out_atoms + (size_t)N * NAF;

    cudaFuncSetAttribute(edge_kernel, cudaFuncAttributeMaxDynamicSharedMemorySize,
                         EDGE_SMEM_BYTES);

    int init_blocks = (N * N + 1023) / 1024;
    init_kernel<<<init_blocks, 1024>>>(N);

    int nodeBlocks = (N + 15) / 16;
    node_fold_kernel<<<nodeBlocks + EDIM + 1, 256>>>(
        s, Ws, bs, W0, Wa, ba, Wb, bb, b0, out_atoms, N, nodeBlocks);

    int scatBlocks = (E + 255) / 256;
    int coordBlocks = (N + 7) / 8;
    prep_kernel<<<scatBlocks + coordBlocks, 256>>>(
        eidx, v, p, Wc, batch, N, E, scatBlocks);

    edge_kernel<<<(E + ETILE - 1) / ETILE, 256, EDGE_SMEM_BYTES>>>(
        e, eidx, batch, W0, W1, b1, out_bonds, N, E);

    finalize_coords_kernel<<<(N * 3 + 255) / 256, 256>>>(batch, out_coords, N);
}

// round 8
// speedup vs baseline: 1.3254x; 1.0064x over previous
#include <cuda_runtime.h>
#include <cuda_bf16.h>
#include <cuda_fp16.h>
#include <cstdint>

#define SDIM 256
#define EDIM 32
#define VDIM 64
#define NMOL 64
#define NAF  16
#define NBT  5
#define MAXN 2048
#define ETILE 128

// ---------------- device scratch ----------------
__device__ float g_sh[MAXN * SDIM];
__device__ float g_T [MAXN * SDIM];
__device__ float g_raw[MAXN * 3];
__device__ float g_sums[NMOL * 3];
__device__ float g_cnt[NMOL];
__device__ int   g_map[MAXN * MAXN];
__device__ float g_wbw0[EDIM * SDIM];      // Wb @ W0'
__device__ float g_cvec[SDIM];             // bb @ W0' + b0

__device__ __forceinline__ float silu_f(float x) {
    return __fdividef(x, 1.0f + __expf(-x));
}
// silu via MUFU.TANH: silu(x) = h + h*tanh(h), h = x/2
__device__ __forceinline__ float silu_t(float x) {
    float h = 0.5f * x;
    float t;
    asm("tanh.approx.f32 %0, %1;" : "=f"(t) : "f"(h));
    return fmaf(h, t, h);
}

// ---------------- k0: init ----------------
__global__ void init_kernel(int N) {
    int idx = blockIdx.x * blockDim.x + threadIdx.x;
    int total = N * N;
    for (int i = idx; i < total; i += gridDim.x * blockDim.x) g_map[i] = -1;
    if (idx < NMOL * 3) g_sums[idx] = 0.0f;
    if (idx < NMOL)     g_cnt[idx]  = 0.0f;
}

// ---------------- k1: fused node work (+foldw tail blocks) ----------------
__global__ __launch_bounds__(256) void node_fold_kernel(
    const float* __restrict__ s, const float* __restrict__ Ws,
    const float* __restrict__ bs, const float* __restrict__ W0,
    const float* __restrict__ Wa, const float* __restrict__ ba,
    const float* __restrict__ Wb, const float* __restrict__ bb,
    const float* __restrict__ b0,
    float* __restrict__ out_atoms, int N, int nodeBlocks)
{
    if (blockIdx.x >= nodeBlocks) {
        int c = threadIdx.x;
        int r = blockIdx.x - nodeBlocks;
        const float* xrow = (r < EDIM) ? (Wb + r * SDIM) : bb;
        float a0 = 0, a1 = 0, a2 = 0, a3 = 0, a4 = 0, a5 = 0, a6 = 0, a7 = 0;
        for (int m = 0; m < SDIM; m += 8) {
            float x0 = xrow[m+0], x1 = xrow[m+1], x2 = xrow[m+2], x3 = xrow[m+3];
            float x4 = xrow[m+4], x5 = xrow[m+5], x6 = xrow[m+6], x7 = xrow[m+7];
            a0 += x0 * W0[(m+0)*SDIM+c]; a1 += x1 * W0[(m+1)*SDIM+c];
            a2 += x2 * W0[(m+2)*SDIM+c]; a3 += x3 * W0[(m+3)*SDIM+c];
            a4 += x4 * W0[(m+4)*SDIM+c]; a5 += x5 * W0[(m+5)*SDIM+c];
            a6 += x6 * W0[(m+6)*SDIM+c]; a7 += x7 * W0[(m+7)*SDIM+c];
        }
        float acc = ((a0+a1)+(a2+a3)) + ((a4+a5)+(a6+a7));
        if (r < EDIM) g_wbw0[r * SDIM + c] = acc;
        else          g_cvec[c] = acc + b0[c];
        return;
    }

    __shared__ float sX[16 * 256];
    __shared__ float sW[32 * 256];
    int tid = threadIdx.x, lane = tid & 31, wp = tid >> 5;
    int row0 = blockIdx.x * 16;

    for (int idx = tid; idx < 16 * 256; idx += 256) {
        int g = row0 * 256 + idx;
        sX[idx] = (g < N * 256) ? s[g] : 0.0f;
    }

    float acc[8][2];
#pragma unroll
    for (int u = 0; u < 8; u++) {
        float b = bs[lane + 32 * u];
        acc[u][0] = b; acc[u][1] = b;
    }
    for (int kc = 0; kc < 8; kc++) {
        __syncthreads();
        for (int idx = tid; idx < 8192; idx += 256)
            sW[idx] = Ws[kc * 32 * 256 + idx];
        __syncthreads();
#pragma unroll
        for (int kk = 0; kk < 32; kk++) {
            float w[8];
#pragma unroll
            for (int u = 0; u < 8; u++) w[u] = sW[kk * 256 + lane + 32 * u];
            float x0 = sX[(wp * 2 + 0) * 256 + kc * 32 + kk];
            float x1 = sX[(wp * 2 + 1) * 256 + kc * 32 + kk];
#pragma unroll
            for (int u = 0; u < 8; u++) {
                acc[u][0] += w[u] * x0;
                acc[u][1] += w[u] * x1;
            }
        }
    }
    __syncthreads();
#pragma unroll
    for (int v = 0; v < 2; v++) {
        int r = row0 + wp * 2 + v;
#pragma unroll
        for (int u = 0; u < 8; u++) {
            float z = silu_f(acc[u][v]);
            sX[(wp * 2 + v) * 256 + lane + 32 * u] = z;
            if (r < N) g_sh[r * 256 + lane + 32 * u] = z;
        }
    }

#pragma unroll
    for (int u = 0; u < 8; u++) { acc[u][0] = 0.0f; acc[u][1] = 0.0f; }
    for (int kc = 0; kc < 8; kc++) {
        __syncthreads();
        for (int idx = tid; idx < 8192; idx += 256)
            sW[idx] = W0[kc * 32 * 256 + idx];
        __syncthreads();
#pragma unroll
        for (int kk = 0; kk < 32; kk++) {
            float w[8];
#pragma unroll
            for (int u = 0; u < 8; u++) w[u] = sW[kk * 256 + lane + 32 * u];
            float x0 = sX[(wp * 2 + 0) * 256 + kc * 32 + kk];
            float x1 = sX[(wp * 2 + 1) * 256 + kc * 32 + kk];
#pragma unroll
            for (int u = 0; u < 8; u++) {
                acc[u][0] += w[u] * x0;
                acc[u][1] += w[u] * x1;
            }
        }
    }
#pragma unroll
    for (int v = 0; v < 2; v++) {
        int r = row0 + wp * 2 + v;
        if (r < N) {
#pragma unroll
            for (int u = 0; u < 8; u++)
                g_T[r * 256 + lane + 32 * u] = acc[u][v];
        }
    }

    __syncthreads();
    for (int idx = tid; idx < SDIM * NAF; idx += 256) sW[idx] = Wa[idx];
    __syncthreads();
#pragma unroll
    for (int v = 0; v < 2; v++) {
        int rl = wp * 2 + v;
        int r = row0 + rl;
        float a[NAF];
#pragma unroll
        for (int q = 0; q < NAF; q++) a[q] = 0.0f;
#pragma unroll
        for (int m = 0; m < 8; m++) {
            int c = lane + 32 * m;
            float x = sX[rl * 256 + c];
#pragma unroll
            for (int q = 0; q < NAF; q++) a[q] += x * sW[c * NAF + q];
        }
#pragma unroll
        for (int q = 0; q < NAF; q++) {
#pragma unroll
            for (int off = 16; off; off >>= 1)
                a[q] += __shfl_xor_sync(0xffffffffu, a[q], off);
        }
        if (r < N && lane < NAF)
            out_atoms[(size_t)r * NAF + lane] = a[lane] + ba[lane];
    }
}

// ---------------- k2: scatter + coords sums ----------------
__global__ void prep_kernel(const int* __restrict__ eidx,
                            const float* __restrict__ v, const float* __restrict__ p,
                            const float* __restrict__ Wc, const int* __restrict__ batch,
                            int N, int E, int scatBlocks)
{
    int tid = threadIdx.x;
    if ((int)blockIdx.x < scatBlocks) {
        int k = blockIdx.x * 256 + tid;
        if (k < E) {
            int j = eidx[k];
            int i = eidx[E + k];
            atomicMax(&g_map[j * N + i], k);
        }
        return;
    }
    int n = (blockIdx.x - scatBlocks) * 8 + (tid >> 5);
    int lane = tid & 31;
    if (n >= N) return;
    const float* vb = v + (size_t)n * 3 * VDIM;
    float w0 = Wc[lane], w1 = Wc[32 + lane];
    float a0 = vb[lane] * w0 + vb[32 + lane] * w1;
    float a1 = vb[64 + lane] * w0 + vb[96 + lane] * w1;
    float a2 = vb[128 + lane] * w0 + vb[160 + lane] * w1;
#pragma unroll
    for (int off = 16; off; off >>= 1) {
        a0 += __shfl_xor_sync(0xffffffffu, a0, off);
        a1 += __shfl_xor_sync(0xffffffffu, a1, off);
        a2 += __shfl_xor_sync(0xffffffffu, a2, off);
    }
    if (lane == 0) {
        int b = batch[n];
        float r0 = p[n * 3 + 0] + a0;
        float r1 = p[n * 3 + 1] + a1;
        float r2 = p[n * 3 + 2] + a2;
        g_raw[n * 3 + 0] = r0; g_raw[n * 3 + 1] = r1; g_raw[n * 3 + 2] = r2;
        atomicAdd(&g_sums[b * 3 + 0], r0);
        atomicAdd(&g_sums[b * 3 + 1], r1);
        atomicAdd(&g_sums[b * 3 + 2], r2);
        atomicAdd(&g_cnt[b], 1.0f);
    }
}

// ---------------- k3 (PROFILED): fused edge network, fp16 weight staging ----------------
// smem floats: sWh(half2) 4096 slots | sW1h(half2) 640 | scv 256 | sw0 256 | sg 4096 | sd 128 | ints 512
#define EDGE_SMEM_BYTES ((4096 + 640 + 256 + 256 + 4096 + 128 + 512) * 4)

__device__ __forceinline__ unsigned long long dup_f32x2(float x) {
    unsigned long long r;
    asm("mov.b64 %0, {%1, %1};" : "=l"(r) : "r"(__float_as_uint(x)));
    return r;
}
__device__ __forceinline__ void ffma2(unsigned long long& acc,
                                      unsigned long long a, unsigned long long b) {
    asm("fma.rn.f32x2 %0, %1, %2, %0;" : "+l"(acc) : "l"(a), "l"(b));
}
__device__ __forceinline__ float2 unpack2(unsigned long long x) {
    float2 r;
    asm("mov.b64 {%0, %1}, %2;" : "=f"(r.x), "=f"(r.y) : "l"(x));
    return r;
}
__device__ __forceinline__ unsigned long long pack2(float x, float y) {
    unsigned long long r;
    asm("mov.b64 %0, {%1, %2};" : "=l"(r) : "r"(__float_as_uint(x)), "r"(__float_as_uint(y)));
    return r;
}
__device__ __forceinline__ unsigned long long h2_to_f32x2(half2 h) {
    float2 f = __half22float2(h);
    return pack2(f.x, f.y);
}

__global__ __launch_bounds__(256, 3) void edge_kernel(
    const float* __restrict__ e, const int* __restrict__ eidx,
    const int* __restrict__ batch,
    const float* __restrict__ W0, const float* __restrict__ W1,
    const float* __restrict__ b1,
    float* __restrict__ out_bonds, int N, int E)
{
    extern __shared__ float sm[];
    half2* sWh  = (half2*)sm;              // [32][128] col-pairs of WbW0 (fp16)
    half2* sW1h = (half2*)(sm + 4096);     // [5][128]  col-pairs of W1^T (fp16)
    float* scv  = sm + 4096 + 640;         // [256]
    float* sw0  = scv + 256;               // [256]
    float* sg   = sw0 + 256;               // [128][32]
    float* sd   = sg + 4096;               // [128]
    int*   sI   = (int*)(sd + 128);
    int*   sJ   = sI + 128;
    int*   sK1  = sJ + 128;
    int*   sK2  = sK1 + 128;

    int tid = threadIdx.x, lane = tid & 31, wp = tid >> 5;
    int e0 = blockIdx.x * ETILE;

    // stage WbW0 as half2 col-pairs: sWh[q*128+p] = (W[q][2p], W[q][2p+1])
    for (int idx = tid; idx < 32 * 128; idx += 256) {
        int q = idx >> 7, p = idx & 127;
        float2 w = *(const float2*)&g_wbw0[q * 256 + 2 * p];
        sWh[idx] = __floats2half2_rn(w.x, w.y);
    }
    // stage W1^T as half2 col-pairs: sW1h[b*128+p] = (W1[2p][b], W1[2p+1][b])
    for (int idx = tid; idx < 5 * 128; idx += 256) {
        int b = idx >> 7, p = idx & 127;
        sW1h[idx] = __floats2half2_rn(W1[(2 * p) * NBT + b], W1[(2 * p + 1) * NBT + b]);
    }
    if (tid < 256) { scv[tid] = g_cvec[tid]; sw0[tid] = W0[256 * 256 + tid]; }

    // ---- per-edge meta (incl. inline centering) ----
    if (tid < ETILE) {
        int eg = e0 + tid;
        int i = 0, j = 0, k1 = -1, k2 = -1;
        float dval = 0.0f;
        if (eg < E) {
            j = eidx[eg];
            i = eidx[E + eg];
            k1 = g_map[j * N + i];
            k2 = g_map[i * N + j];
            int bi = batch[i], bj = batch[j];
            float inv_i = 1.0f / fmaxf(g_cnt[bi], 1.0f);
            float inv_j = 1.0f / fmaxf(g_cnt[bj], 1.0f);
            float dx = (g_raw[i*3+0] - g_sums[bi*3+0]*inv_i)
                     - (g_raw[j*3+0] - g_sums[bj*3+0]*inv_j);
            float dy = (g_raw[i*3+1] - g_sums[bi*3+1]*inv_i)
                     - (g_raw[j*3+1] - g_sums[bj*3+1]*inv_j);
            float dz = (g_raw[i*3+2] - g_sums[bi*3+2]*inv_i)
                     - (g_raw[j*3+2] - g_sums[bj*3+2]*inv_j);
            dval = dx * dx + dy * dy + dz * dz;
        }
        sI[tid] = i; sJ[tid] = j; sK1[tid] = k1; sK2[tid] = k2; sd[tid] = dval;
    }
    __syncthreads();

    // ---- symmetrized e rows ----
    for (int idx = tid; idx < ETILE * 32; idx += 256) {
        int el = idx >> 5, q = idx & 31;
        int k1 = sK1[el], k2 = sK2[el];
        float g1 = (k1 >= 0) ? e[(size_t)k1 * EDIM + q] : 0.0f;
        float g2 = (k2 >= 0) ? e[(size_t)k2 * EDIM + q] : 0.0f;
        sg[idx] = 0.5f * (g1 + g2);
    }
    __syncthreads();

    // ---- each warp: 16 edges, 4 subpasses of 4 ----
    for (int sub = 0; sub < 4; sub++) {
        int base = wp * 16 + sub * 4;

        float gv[4];
#pragma unroll
        for (int v = 0; v < 4; v++) gv[v] = sg[(base + v) * 32 + lane];

        unsigned long long acc[4][4];
#pragma unroll
        for (int t = 0; t < 4; t++)
#pragma unroll
            for (int v = 0; v < 4; v++) acc[t][v] = 0ull;

#pragma unroll 8
        for (int q = 0; q < 32; q++) {
            unsigned long long wq[4];
#pragma unroll
            for (int t = 0; t < 4; t++)
                wq[t] = h2_to_f32x2(sWh[q * 128 + lane + 32 * t]);
#pragma unroll
            for (int v = 0; v < 4; v++) {
                float gq = __shfl_sync(0xffffffffu, gv[v], q);
                unsigned long long g2 = dup_f32x2(gq);
#pragma unroll
                for (int t = 0; t < 4; t++) ffma2(acc[t][v], wq[t], g2);
            }
        }

        // ---- epilogue per edge ----
#pragma unroll
        for (int v = 0; v < 4; v++) {
            int el = base + v;
            int eg = e0 + el;
            int i = sI[el], jn = sJ[el];
            float dval = sd[el];
            const float* Ti = g_T + (size_t)i * 256;
            const float* Tj = g_T + (size_t)jn * 256;

            unsigned long long pbp[NBT];
#pragma unroll
            for (int b = 0; b < NBT; b++) pbp[b] = 0ull;

#pragma unroll
            for (int t = 0; t < 4; t++) {
                int c0 = 2 * lane + 64 * t;
                float2 a  = unpack2(acc[t][v]);
                float2 ti = *(const float2*)&Ti[c0];
                float2 tj = *(const float2*)&Tj[c0];
                float2 cv = *(const float2*)&scv[c0];
                float2 wd = *(const float2*)&sw0[c0];
                float y0 = a.x + cv.x + ti.x + tj.x + dval * wd.x;
                float y1 = a.y + cv.y + ti.y + tj.y + dval * wd.y;
                float z0 = silu_t(y0);
                float z1 = silu_t(y1);
                unsigned long long zp = pack2(z0, z1);
#pragma unroll
                for (int b = 0; b < NBT; b++) {
                    unsigned long long w1p =
                        h2_to_f32x2(sW1h[b * 128 + lane + 32 * t]);
                    ffma2(pbp[b], zp, w1p);
                }
            }
            float pb[NBT];
#pragma unroll
            for (int b = 0; b < NBT; b++) {
                float2 u = unpack2(pbp[b]);
                pb[b] = u.x + u.y;
            }
#pragma unroll
            for (int b = 0; b < NBT; b++) {
#pragma unroll
                for (int off = 16; off; off >>= 1)
                    pb[b] += __shfl_xor_sync(0xffffffffu, pb[b], off);
            }
            if (lane == 0 && eg < E) {
#pragma unroll
                for (int b = 0; b < NBT; b++)
                    out_bonds[(size_t)eg * NBT + b] = pb[b] + b1[b];
            }
        }
    }
}

// ---------------- k4: finalize coords output ----------------
__global__ void finalize_coords_kernel(const int* __restrict__ batch,
                                       float* __restrict__ out_coords, int N)
{
    int idx = blockIdx.x * blockDim.x + threadIdx.x;
    if (idx >= N * 3) return;
    int n = idx / 3, d = idx % 3;
    int b = batch[n];
    float m = g_sums[b * 3 + d] / fmaxf(g_cnt[b], 1.0f);
    out_coords[idx] = g_raw[idx] - m;
}

// ---------------- launch ----------------
extern "C" void kernel_launch(void* const* d_in, const int* in_sizes, int n_in,
                              void* d_out, int out_size)
{
    const float* s     = (const float*)d_in[0];
    const float* v     = (const float*)d_in[1];
    const float* p     = (const float*)d_in[2];
    const float* e     = (const float*)d_in[3];
    const int*   batch = (const int*)d_in[4];
    const int*   eidx  = (const int*)d_in[5];
    const float* Ws = (const float*)d_in[6];
    const float* bs = (const float*)d_in[7];
    const float* Wc = (const float*)d_in[8];
    const float* Wa = (const float*)d_in[9];
    const float* ba = (const float*)d_in[10];
    const float* Wb = (const float*)d_in[11];
    const float* bb = (const float*)d_in[12];
    const float* W0 = (const float*)d_in[13];
    const float* b0 = (const float*)d_in[14];
    const float* W1 = (const float*)d_in[15];
    const float* b1 = (const float*)d_in[16];

    int N = in_sizes[0] / SDIM;
    int E = in_sizes[5] / 2;

    float* out        = (float*)d_out;
    float* out_coords = out;
    float* out_atoms  = out + (size_t)N * 3;
    float* out_bonds  = out_atoms + (size_t)N * NAF;

    cudaFuncSetAttribute(edge_kernel, cudaFuncAttributeMaxDynamicSharedMemorySize,
                         EDGE_SMEM_BYTES);

    int init_blocks = (N * N + 1023) / 1024;
    init_kernel<<<init_blocks, 1024>>>(N);

    int nodeBlocks = (N + 15) / 16;
    node_fold_kernel<<<nodeBlocks + EDIM + 1, 256>>>(
        s, Ws, bs, W0, Wa, ba, Wb, bb, b0, out_atoms, N, nodeBlocks);

    int scatBlocks = (E + 255) / 256;
    int coordBlocks = (N + 7) / 8;
    prep_kernel<<<scatBlocks + coordBlocks, 256>>>(
        eidx, v, p, Wc, batch, N, E, scatBlocks);

    edge_kernel<<<(E + ETILE - 1) / ETILE, 256, EDGE_SMEM_BYTES>>>(
        e, eidx, batch, W0, W1, b1, out_bonds, N, E);

    finalize_coords_kernel<<<(N * 3 + 255) / 256, 256>>>(batch, out_coords, N);
}